// round 1
// baseline (speedup 1.0000x reference)
#include <cuda_runtime.h>
#include <math.h>

#define Bb 2
#define Ll 1024
#define Dd 512
#define Hh 8
#define hh 64
#define EPSF 1e-5f

// -------- scratch (device globals; no allocation allowed) --------
__device__ float g_q [Bb*Hh*Ll*hh];
__device__ float g_k [Bb*Hh*Ll*hh];
__device__ float g_v [Bb*Hh*Ll*hh];
__device__ float g_kc[Bb*Hh*Ll*hh];
__device__ float g_vc[Bb*Hh*Ll*hh];
__device__ float g_gate[Bb*Hh*Ll];
__device__ float g_w   [Bb*Hh*Ll];
__device__ float g_Spart[4*Bb*Hh*hh*hh];
__device__ float g_unit[Bb*Ll*Dd];

// =====================================================================
// K1: fused QKV projection. C[2048,1536] = x @ [wq|wk|wv] + bias,
// scattered into [B,H,L,h] layout; k scaled by h^-0.5 = 0.125.
// =====================================================================
__global__ __launch_bounds__(256) void proj_kernel(
    const float* __restrict__ x,
    const float* __restrict__ wq, const float* __restrict__ bq,
    const float* __restrict__ wk, const float* __restrict__ bk,
    const float* __restrict__ wv, const float* __restrict__ bv)
{
    __shared__ float As[16][68];
    __shared__ float Bs[16][68];
    const int row0 = blockIdx.y * 64;
    const int col0 = blockIdx.x * 64;
    const int mat  = col0 >> 9;                 // 0=q, 1=k, 2=v
    const float* W    = (mat == 0) ? wq : (mat == 1) ? wk : wv;
    const float* bias = (mat == 0) ? bq : (mat == 1) ? bk : bv;
    const int lc0 = col0 & 511;
    const int tid = threadIdx.x;
    const int tx = tid & 15, ty = tid >> 4;
    float acc[4][4] = {};

    const int ar = tid >> 2;
    const int ac = (tid & 3) << 2;
    const int bk_ = tid >> 4;
    const int bn  = (tid & 15) << 2;

    for (int k0 = 0; k0 < 512; k0 += 16) {
        float4 a4 = *(const float4*)(x + (row0 + ar) * 512 + k0 + ac);
        As[ac + 0][ar] = a4.x; As[ac + 1][ar] = a4.y;
        As[ac + 2][ar] = a4.z; As[ac + 3][ar] = a4.w;
        float4 b4 = *(const float4*)(W + (k0 + bk_) * 512 + lc0 + bn);
        *(float4*)&Bs[bk_][bn] = b4;
        __syncthreads();
        #pragma unroll
        for (int kk = 0; kk < 16; kk++) {
            float4 a = *(const float4*)&As[kk][ty * 4];
            float4 b = *(const float4*)&Bs[kk][tx * 4];
            float aa[4] = {a.x, a.y, a.z, a.w};
            float bb[4] = {b.x, b.y, b.z, b.w};
            #pragma unroll
            for (int i = 0; i < 4; i++)
                #pragma unroll
                for (int j = 0; j < 4; j++)
                    acc[i][j] += aa[i] * bb[j];
        }
        __syncthreads();
    }
    float* dst = (mat == 0) ? g_q : (mat == 1) ? g_k : g_v;
    const float scale = (mat == 1) ? 0.125f : 1.0f;
    #pragma unroll
    for (int i = 0; i < 4; i++) {
        int r = row0 + ty * 4 + i;
        int b = r >> 10, l = r & 1023;
        #pragma unroll
        for (int j = 0; j < 4; j++) {
            int lcol = lc0 + tx * 4 + j;
            int head = lcol >> 6, m = lcol & 63;
            float v = (acc[i][j] + bias[lcol]) * scale;
            dst[((b * Hh + head) * Ll + l) * hh + m] = v;
        }
    }
}

// =====================================================================
// K2: causal conv as lower-triangular Toeplitz matmul.
// y[l,m] = sum_{t<=l} filt[head][l-t] * u[t,m], for k and v together.
// =====================================================================
__global__ __launch_bounds__(256) void conv_kernel(const float* __restrict__ sb)
{
    __shared__ float Ks[64][68];
    __shared__ float Vs[64][68];
    __shared__ float fs[128];
    const int b = blockIdx.z, head = blockIdx.y;
    const int L0 = blockIdx.x * 64;
    const int base = ((b * Hh + head) * Ll) * hh;
    const float* kin = g_k + base;
    const float* vin = g_v + base;
    const int tid = threadIdx.x;
    const int tx = tid & 15, ty = tid >> 4;
    float ak[4][4] = {}, av[4][4] = {};

    for (int T0 = 0; T0 <= L0; T0 += 64) {
        for (int i = tid; i < 64 * 16; i += 256) {
            int r = i >> 4, c = (i & 15) << 2;
            *(float4*)&Ks[r][c] = *(const float4*)(kin + (T0 + r) * 64 + c);
            *(float4*)&Vs[r][c] = *(const float4*)(vin + (T0 + r) * 64 + c);
        }
        if (tid < 128) {
            int d = L0 - T0 - 63 + tid;          // filter lag
            fs[tid] = (d >= 0 && d < Ll) ? sb[d * Hh + head] : 0.0f;
        }
        __syncthreads();
        #pragma unroll 4
        for (int tt = 0; tt < 64; tt++) {
            float f[4];
            #pragma unroll
            for (int i = 0; i < 4; i++) f[i] = fs[ty * 4 + i - tt + 63];
            float4 kq = *(const float4*)&Ks[tt][tx * 4];
            float4 vq = *(const float4*)&Vs[tt][tx * 4];
            float kv[4] = {kq.x, kq.y, kq.z, kq.w};
            float vv[4] = {vq.x, vq.y, vq.z, vq.w};
            #pragma unroll
            for (int i = 0; i < 4; i++)
                #pragma unroll
                for (int j = 0; j < 4; j++) {
                    ak[i][j] += f[i] * kv[j];
                    av[i][j] += f[i] * vv[j];
                }
        }
        __syncthreads();
    }
    float* kdst = g_kc + base;
    float* vdst = g_vc + base;
    #pragma unroll
    for (int i = 0; i < 4; i++) {
        int l = L0 + ty * 4 + i;
        #pragma unroll
        for (int j = 0; j < 4; j++) {
            int m = tx * 4 + j;
            kdst[l * 64 + m] = ak[i][j];
            vdst[l * 64 + m] = av[i][j];
        }
    }
}

// =====================================================================
// K3: gates. gate[l] = relu(v_conv[l]^T W k_conv[l] + b)^2 + eps
// One thread per (b,h,l). W (64x64) broadcast from smem.
// =====================================================================
__global__ __launch_bounds__(256) void gate_kernel(
    const float* __restrict__ wg, const float* __restrict__ wgb)
{
    __shared__ float Wg[64][64];
    const int tid = threadIdx.x;
    for (int i = tid; i < 4096; i += 256) Wg[i >> 6][i & 63] = wg[i];
    __syncthreads();

    const int gidx = blockIdx.x * 256 + tid;   // (b*H+h)*L + l
    const float* vr = g_vc + gidx * 64;
    const float* kr = g_kc + gidx * 64;
    float kreg[64];
    #pragma unroll
    for (int n = 0; n < 64; n++) kreg[n] = kr[n];
    float acc = 0.0f;
    for (int m = 0; m < 64; m++) {
        float dot = 0.0f;
        #pragma unroll
        for (int n = 0; n < 64; n++) dot += Wg[m][n] * kreg[n];
        acc += vr[m] * dot;
    }
    acc += wgb[0];
    float rl = fmaxf(acc, 0.0f);
    g_gate[gidx] = rl * rl + EPSF;
}

// =====================================================================
// K4: scans. cumG = cumsum(gate); r = 1/(cumG+eps); c = suffix-sum(r);
// w[t] = gate[t]*c[t]. One block per (b,h), 256 threads, 1024 elems.
// =====================================================================
__device__ __forceinline__ void block_scan_1024(float* arr, float* wsum)
{
    const int tid = threadIdx.x;
    const int lane = tid & 31, wid = tid >> 5;
    float v0 = arr[tid * 4 + 0], v1 = arr[tid * 4 + 1];
    float v2 = arr[tid * 4 + 2], v3 = arr[tid * 4 + 3];
    v1 += v0; v2 += v1; v3 += v2;
    float s = v3;
    #pragma unroll
    for (int o = 1; o < 32; o <<= 1) {
        float t = __shfl_up_sync(0xffffffff, s, o);
        if (lane >= o) s += t;
    }
    float excl = s - v3;
    if (lane == 31) wsum[wid] = s;
    __syncthreads();
    if (wid == 0) {
        float ws = (lane < 8) ? wsum[lane] : 0.0f;
        #pragma unroll
        for (int o = 1; o < 8; o <<= 1) {
            float t = __shfl_up_sync(0xffffffff, ws, o);
            if (lane >= o) ws += t;
        }
        if (lane < 8) wsum[lane] = ws;
    }
    __syncthreads();
    float base = ((wid > 0) ? wsum[wid - 1] : 0.0f) + excl;
    arr[tid * 4 + 0] = v0 + base;
    arr[tid * 4 + 1] = v1 + base;
    arr[tid * 4 + 2] = v2 + base;
    arr[tid * 4 + 3] = v3 + base;
    __syncthreads();
}

__global__ __launch_bounds__(256) void scan_kernel()
{
    __shared__ float g[1024];
    __shared__ float p[1024];
    __shared__ float r[1024];
    __shared__ float ws[8];
    const int bh = blockIdx.x;
    const int tid = threadIdx.x;
    const float* gin = g_gate + bh * 1024;
    for (int i = tid; i < 1024; i += 256) { float v = gin[i]; g[i] = v; p[i] = v; }
    __syncthreads();
    block_scan_1024(p, ws);                       // p = inclusive cumG
    for (int i = tid; i < 1024; i += 256) r[i] = 1.0f / (p[i] + EPSF);
    __syncthreads();
    for (int i = tid; i < 1024; i += 256) p[i] = r[i];
    __syncthreads();
    block_scan_1024(p, ws);                       // p = inclusive prefix of r
    float total = p[1023];
    for (int i = tid; i < 1024; i += 256) {
        float c = total - p[i] + r[i];             // suffix sum of r
        g_w[bh * 1024 + i] = g[i] * c;
    }
}

// =====================================================================
// K5: S partials. S[m,n] = sum_t w[t] v_conv[t,m] k_conv[t,n].
// grid (4 t-chunks, 16 bh), each block accumulates over 256 t's.
// =====================================================================
__global__ __launch_bounds__(256) void Spart_kernel()
{
    __shared__ float Vs[64][68];
    __shared__ float Ks[64][68];
    const int tc = blockIdx.x, bh = blockIdx.y;
    const float* vin = g_vc + bh * Ll * hh;
    const float* kin = g_kc + bh * Ll * hh;
    const float* wt  = g_w  + bh * Ll;
    const int tid = threadIdx.x;
    const int tx = tid & 15, ty = tid >> 4;
    float acc[4][4] = {};

    for (int T0 = tc * 256; T0 < tc * 256 + 256; T0 += 64) {
        for (int i = tid; i < 64 * 16; i += 256) {
            int rrow = i >> 4, c = (i & 15) << 2;
            float w = wt[T0 + rrow];
            float4 vv = *(const float4*)(vin + (T0 + rrow) * 64 + c);
            vv.x *= w; vv.y *= w; vv.z *= w; vv.w *= w;
            *(float4*)&Vs[rrow][c] = vv;
            *(float4*)&Ks[rrow][c] = *(const float4*)(kin + (T0 + rrow) * 64 + c);
        }
        __syncthreads();
        #pragma unroll 4
        for (int tt = 0; tt < 64; tt++) {
            float4 a4 = *(const float4*)&Vs[tt][ty * 4];
            float4 b4 = *(const float4*)&Ks[tt][tx * 4];
            float aa[4] = {a4.x, a4.y, a4.z, a4.w};
            float bb[4] = {b4.x, b4.y, b4.z, b4.w};
            #pragma unroll
            for (int i = 0; i < 4; i++)
                #pragma unroll
                for (int j = 0; j < 4; j++)
                    acc[i][j] += aa[i] * bb[j];
        }
        __syncthreads();
    }
    float* dst = g_Spart + (tc * 16 + bh) * 4096;
    #pragma unroll
    for (int i = 0; i < 4; i++)
        #pragma unroll
        for (int j = 0; j < 4; j++)
            dst[(ty * 4 + i) * 64 + tx * 4 + j] = acc[i][j];
}

// =====================================================================
// K6: ctxt = q @ S, row-normalize, scatter to [B,L,D] layout.
// =====================================================================
__global__ __launch_bounds__(256) void ctxt_kernel()
{
    __shared__ float Ss[64][65];
    const int b = blockIdx.z, head = blockIdx.y, lc = blockIdx.x;
    const int bh = b * Hh + head;
    const int tid = threadIdx.x;
    for (int i = tid; i < 4096; i += 256) {
        float s = 0.0f;
        #pragma unroll
        for (int p = 0; p < 4; p++) s += g_Spart[(p * 16 + bh) * 4096 + i];
        Ss[i >> 6][i & 63] = s;
    }
    __syncthreads();
    const int l = lc * 256 + tid;
    const float* qrow = g_q + (bh * Ll + l) * hh;
    float out[64];
    #pragma unroll
    for (int e = 0; e < 64; e++) out[e] = 0.0f;
    for (int d = 0; d < 64; d++) {
        float qd = qrow[d];
        #pragma unroll
        for (int e = 0; e < 64; e++) out[e] += qd * Ss[d][e];
    }
    float nrm = 0.0f;
    #pragma unroll
    for (int e = 0; e < 64; e++) nrm += out[e] * out[e];
    float inv = 1.0f / fmaxf(sqrtf(nrm), EPSF);
    float* dst = g_unit + (b * Ll + l) * Dd + head * hh;
    #pragma unroll
    for (int e = 0; e < 64; e++) dst[e] = out[e] * inv;
}

// =====================================================================
// K7: output projection. out[2048,512] = g_unit @ wo + bo.
// =====================================================================
__global__ __launch_bounds__(256) void out_gemm_kernel(
    const float* __restrict__ wo, const float* __restrict__ bo,
    float* __restrict__ out)
{
    __shared__ float As[16][68];
    __shared__ float Bs[16][68];
    const int row0 = blockIdx.y * 64;
    const int col0 = blockIdx.x * 64;
    const int tid = threadIdx.x;
    const int tx = tid & 15, ty = tid >> 4;
    float acc[4][4] = {};
    const int ar = tid >> 2;
    const int ac = (tid & 3) << 2;
    const int bk_ = tid >> 4;
    const int bn  = (tid & 15) << 2;

    for (int k0 = 0; k0 < 512; k0 += 16) {
        float4 a4 = *(const float4*)(g_unit + (row0 + ar) * 512 + k0 + ac);
        As[ac + 0][ar] = a4.x; As[ac + 1][ar] = a4.y;
        As[ac + 2][ar] = a4.z; As[ac + 3][ar] = a4.w;
        float4 b4 = *(const float4*)(wo + (k0 + bk_) * 512 + col0 + bn);
        *(float4*)&Bs[bk_][bn] = b4;
        __syncthreads();
        #pragma unroll
        for (int kk = 0; kk < 16; kk++) {
            float4 a = *(const float4*)&As[kk][ty * 4];
            float4 b = *(const float4*)&Bs[kk][tx * 4];
            float aa[4] = {a.x, a.y, a.z, a.w};
            float bb[4] = {b.x, b.y, b.z, b.w};
            #pragma unroll
            for (int i = 0; i < 4; i++)
                #pragma unroll
                for (int j = 0; j < 4; j++)
                    acc[i][j] += aa[i] * bb[j];
        }
        __syncthreads();
    }
    #pragma unroll
    for (int i = 0; i < 4; i++) {
        int r = row0 + ty * 4 + i;
        #pragma unroll
        for (int j = 0; j < 4; j++) {
            int c = col0 + tx * 4 + j;
            out[r * 512 + c] = acc[i][j] + bo[c];
        }
    }
}

// =====================================================================
extern "C" void kernel_launch(void* const* d_in, const int* in_sizes, int n_in,
                              void* d_out, int out_size)
{
    const float* x   = (const float*)d_in[0];
    const float* sb  = (const float*)d_in[1];
    const float* wq  = (const float*)d_in[2];
    const float* bq  = (const float*)d_in[3];
    const float* wk  = (const float*)d_in[4];
    const float* bk  = (const float*)d_in[5];
    const float* wv  = (const float*)d_in[6];
    const float* bv  = (const float*)d_in[7];
    const float* wo  = (const float*)d_in[8];
    const float* bo  = (const float*)d_in[9];
    const float* wg  = (const float*)d_in[10];
    const float* wgb = (const float*)d_in[11];
    float* out = (float*)d_out;

    proj_kernel<<<dim3(24, 32), 256>>>(x, wq, bq, wk, bk, wv, bv);
    conv_kernel<<<dim3(16, 8, 2), 256>>>(sb);
    gate_kernel<<<64, 256>>>(wg, wgb);
    scan_kernel<<<16, 256>>>();
    Spart_kernel<<<dim3(4, 16), 256>>>();
    ctxt_kernel<<<dim3(4, 8, 2), 256>>>();
    out_gemm_kernel<<<dim3(8, 32), 256>>>(wo, bo, out);
}

// round 3
// speedup vs baseline: 1.3924x; 1.3924x over previous
#include <cuda_runtime.h>
#include <cuda_bf16.h>
#include <cstdint>
#include <math.h>

#define Bb 2
#define Ll 1024
#define Dd 512
#define Hh 8
#define hh 64
#define EPSF 1e-5f

// ---------------- scratch (device globals; no runtime allocation) ----------------
__device__ __nv_bfloat16 g_xhi[2048*512], g_xlo[2048*512];
__device__ __nv_bfloat16 g_wqkvT_hi[1536*512], g_wqkvT_lo[1536*512];
__device__ __nv_bfloat16 g_woT_hi[512*512],  g_woT_lo[512*512];
__device__ __nv_bfloat16 g_ktr_hi[16*64*1024], g_ktr_lo[16*64*1024];
__device__ __nv_bfloat16 g_vtr_hi[16*64*1024], g_vtr_lo[16*64*1024];
__device__ __nv_bfloat16 g_uhi[2048*512], g_ulo[2048*512];
__device__ float g_q [16*1024*64];
__device__ float g_kc[16*1024*64];
__device__ float g_vc[16*1024*64];
__device__ float g_gate[16*1024];
__device__ float g_w   [16*1024];
__device__ float g_Spart[4*16*64*64];

// ---------------- helpers ----------------
__device__ __forceinline__ uint32_t smem_u32(const void* p){
    uint32_t a;
    asm("{ .reg .u64 t; cvta.to.shared.u64 t, %1; cvt.u32.u64 %0, t; }" : "=r"(a) : "l"(p));
    return a;
}

#define LDSM_X4(d0,d1,d2,d3,addr) \
    asm volatile("ldmatrix.sync.aligned.m8n8.x4.shared.b16 {%0,%1,%2,%3}, [%4];" \
        : "=r"(d0),"=r"(d1),"=r"(d2),"=r"(d3) : "r"(addr))

__device__ __forceinline__ void mma_bf16(float* c, const uint32_t* a, uint32_t b0, uint32_t b1){
    asm volatile(
        "mma.sync.aligned.m16n8k16.row.col.f32.bf16.bf16.f32 "
        "{%0,%1,%2,%3},{%4,%5,%6,%7},{%8,%9},{%0,%1,%2,%3};"
        : "+f"(c[0]),"+f"(c[1]),"+f"(c[2]),"+f"(c[3])
        : "r"(a[0]),"r"(a[1]),"r"(a[2]),"r"(a[3]),"r"(b0),"r"(b1));
}

__device__ __forceinline__ void split_bf(float v, __nv_bfloat16& h, __nv_bfloat16& l){
    h = __float2bfloat16(v);
    l = __float2bfloat16(v - __bfloat162float(h));
}

// smem tile geometry: rows padded to 40 bf16 (80B) -> conflict-free ldmatrix
#define LDAe 40
#define TILE_B 10240              // 128 * 40 * 2
#define BUF_B  40960              // Ah | Al | Bh | Bl

// core: one 32-deep K chunk of bf16x3 MMA. acc[2][8][4].
__device__ __forceinline__ void mma_chunk(
    uint32_t Ah, uint32_t Al, uint32_t Bh, uint32_t Bl,
    int warpM, int warpN, int lane, float acc[2][8][4])
{
    const int rsub = ((lane >> 3) & 1) * 8 + (lane & 7);
    const int ksel = (lane >> 4) * 8;
    #pragma unroll
    for (int ks = 0; ks < 32; ks += 16){
        uint32_t ah[2][4], al[2][4], bh[4][4], bl[4][4];
        #pragma unroll
        for (int mt = 0; mt < 2; mt++){
            uint32_t off = ((warpM*32 + mt*16 + rsub) * LDAe + ks + ksel) * 2;
            LDSM_X4(ah[mt][0],ah[mt][1],ah[mt][2],ah[mt][3], Ah + off);
            LDSM_X4(al[mt][0],al[mt][1],al[mt][2],al[mt][3], Al + off);
        }
        #pragma unroll
        for (int np = 0; np < 4; np++){
            uint32_t off = ((warpN*64 + np*16 + rsub) * LDAe + ks + ksel) * 2;
            LDSM_X4(bh[np][0],bh[np][1],bh[np][2],bh[np][3], Bh + off);
            LDSM_X4(bl[np][0],bl[np][1],bl[np][2],bl[np][3], Bl + off);
        }
        #pragma unroll
        for (int mt = 0; mt < 2; mt++)
            #pragma unroll
            for (int nt = 0; nt < 8; nt++){
                int np = nt >> 1, s = nt & 1;
                uint32_t b0h = bh[np][s], b1h = bh[np][s+2];
                uint32_t b0l = bl[np][s], b1l = bl[np][s+2];
                mma_bf16(acc[mt][nt], ah[mt], b0h, b1h);
                mma_bf16(acc[mt][nt], al[mt], b0h, b1h);
                mma_bf16(acc[mt][nt], ah[mt], b0l, b1l);
            }
    }
}

// load one 128x32 bf16 tile (row-major src, stride elems) into padded smem
__device__ __forceinline__ void load_tile(char* dst, const __nv_bfloat16* src, int stride, int tid){
    #pragma unroll
    for (int j = 0; j < 2; j++){
        int i = tid + j * 256;
        int r = i >> 2, seg = (i & 3) * 8;
        float4 v = *(const float4*)(src + (long)r * stride + seg);
        *(float4*)(dst + (r * LDAe + seg) * 2) = v;
    }
}

// =====================================================================
// P1: x -> bf16 hi/lo
// =====================================================================
__global__ __launch_bounds__(256) void prep_x(const float* __restrict__ x)
{
    int i = blockIdx.x * 256 + threadIdx.x;
    float4 v = ((const float4*)x)[i];
    __nv_bfloat16 h0,l0,h1,l1,h2,l2,h3,l3;
    split_bf(v.x,h0,l0); split_bf(v.y,h1,l1); split_bf(v.z,h2,l2); split_bf(v.w,h3,l3);
    ((__nv_bfloat162*)g_xhi)[i*2+0] = __halves2bfloat162(h0,h1);
    ((__nv_bfloat162*)g_xhi)[i*2+1] = __halves2bfloat162(h2,h3);
    ((__nv_bfloat162*)g_xlo)[i*2+0] = __halves2bfloat162(l0,l1);
    ((__nv_bfloat162*)g_xlo)[i*2+1] = __halves2bfloat162(l2,l3);
}

// =====================================================================
// P2: transpose+convert weights
// =====================================================================
__global__ __launch_bounds__(256) void prep_w(
    const float* __restrict__ wq, const float* __restrict__ wk,
    const float* __restrict__ wv, const float* __restrict__ wo)
{
    __shared__ float s[64][65];
    int bx = blockIdx.x;
    int k0 = blockIdx.y * 64;
    const float* W; __nv_bfloat16 *Dh, *Dl; int n0; int dstRow0;
    if (bx < 24) {
        int ng0 = bx * 64; int mat = ng0 >> 9;
        W = (mat == 0) ? wq : (mat == 1) ? wk : wv;
        n0 = ng0 & 511; dstRow0 = ng0;
        Dh = g_wqkvT_hi; Dl = g_wqkvT_lo;
    } else {
        W = wo; n0 = (bx - 24) * 64; dstRow0 = n0;
        Dh = g_woT_hi; Dl = g_woT_lo;
    }
    int tid = threadIdx.x;
    #pragma unroll
    for (int i = 0; i < 4; i++){
        int r = i * 16 + (tid >> 4);
        int c = (tid & 15) * 4;
        float4 v = *(const float4*)(W + (k0 + r) * 512 + n0 + c);
        s[r][c+0]=v.x; s[r][c+1]=v.y; s[r][c+2]=v.z; s[r][c+3]=v.w;
    }
    __syncthreads();
    #pragma unroll
    for (int i = 0; i < 4; i++){
        int rn = i * 16 + (tid >> 4);
        int ck = (tid & 15) * 4;
        __nv_bfloat16 h[4], l[4];
        #pragma unroll
        for (int j = 0; j < 4; j++) split_bf(s[ck + j][rn], h[j], l[j]);
        int off = (dstRow0 + rn) * 512 + k0 + ck;
        *(__nv_bfloat162*)(Dh + off)     = __halves2bfloat162(h[0], h[1]);
        *(__nv_bfloat162*)(Dh + off + 2) = __halves2bfloat162(h[2], h[3]);
        *(__nv_bfloat162*)(Dl + off)     = __halves2bfloat162(l[0], l[1]);
        *(__nv_bfloat162*)(Dl + off + 2) = __halves2bfloat162(l[2], l[3]);
    }
}

// =====================================================================
// K1: QKV projection GEMM (bf16x3 mma.sync). C tile 128 tok x 128 feat.
// =====================================================================
__global__ __launch_bounds__(256) void proj_mma(
    const float* __restrict__ bq, const float* __restrict__ bk, const float* __restrict__ bv)
{
    extern __shared__ char sm[];
    const uint32_t sb = smem_u32(sm);
    const int tid = threadIdx.x;
    const int lane = tid & 31, wid = tid >> 5;
    const int warpM = wid & 3, warpN = wid >> 2;
    const int row0 = blockIdx.y * 128;
    const int n0   = blockIdx.x * 128;

    float acc[2][8][4] = {};

    // chunk 0
    {
        char* tb = sm;
        load_tile(tb,            g_xhi + (long)row0*512, 512, tid);
        load_tile(tb +   TILE_B, g_xlo + (long)row0*512, 512, tid);
        load_tile(tb + 2*TILE_B, g_wqkvT_hi + (long)n0*512, 512, tid);
        load_tile(tb + 3*TILE_B, g_wqkvT_lo + (long)n0*512, 512, tid);
    }
    __syncthreads();
    for (int c = 0; c < 16; c++){
        if (c + 1 < 16){
            char* tb = sm + ((c + 1) & 1) * BUF_B;
            int k0 = (c + 1) * 32;
            load_tile(tb,            g_xhi + (long)row0*512 + k0, 512, tid);
            load_tile(tb +   TILE_B, g_xlo + (long)row0*512 + k0, 512, tid);
            load_tile(tb + 2*TILE_B, g_wqkvT_hi + (long)n0*512 + k0, 512, tid);
            load_tile(tb + 3*TILE_B, g_wqkvT_lo + (long)n0*512 + k0, 512, tid);
        }
        uint32_t o = sb + (c & 1) * BUF_B;
        mma_chunk(o, o + TILE_B, o + 2*TILE_B, o + 3*TILE_B, warpM, warpN, lane, acc);
        __syncthreads();
    }

    // epilogue
    const int g   = lane >> 2;
    const int tig = lane & 3;
    const int nwarp = n0 + warpN * 64;
    const int mat  = nwarp >> 9;
    const int head = (nwarp >> 6) & 7;
    const int mrow = row0 + warpM * 32;

    if (mat == 0){
        #pragma unroll
        for (int mt = 0; mt < 2; mt++)
            #pragma unroll
            for (int nt = 0; nt < 8; nt++){
                int col = nt * 8 + tig * 2;
                float b0 = bq[(nwarp & 511) + col], b1 = bq[(nwarp & 511) + col + 1];
                #pragma unroll
                for (int rr = 0; rr < 2; rr++){
                    int row = mrow + mt*16 + g + rr*8;
                    int b = row >> 10, l = row & 1023;
                    float2 o; o.x = acc[mt][nt][rr*2+0] + b0; o.y = acc[mt][nt][rr*2+1] + b1;
                    *(float2*)(g_q + (((long)(b*8+head) << 10) + l) * 64 + col) = o;
                }
            }
    } else {
        const float sc = (mat == 1) ? 0.125f : 1.0f;
        const float* bias = (mat == 1) ? bk : bv;
        __nv_bfloat16* Dh = (mat == 1) ? g_ktr_hi : g_vtr_hi;
        __nv_bfloat16* Dl = (mat == 1) ? g_ktr_lo : g_vtr_lo;
        #pragma unroll
        for (int mt = 0; mt < 2; mt++)
            #pragma unroll
            for (int nt = 0; nt < 8; nt++){
                int col = nt * 8 + tig * 2;
                float b0 = bias[(nwarp & 511) + col], b1 = bias[(nwarp & 511) + col + 1];
                #pragma unroll
                for (int rr = 0; rr < 2; rr++){
                    int row = mrow + mt*16 + g + rr*8;
                    int b = row >> 10, l = row & 1023;
                    int bh = b * 8 + head;
                    float v0 = (acc[mt][nt][rr*2+0] + b0) * sc;
                    float v1 = (acc[mt][nt][rr*2+1] + b1) * sc;
                    __nv_bfloat16 h0,l0,h1,l1;
                    split_bf(v0,h0,l0); split_bf(v1,h1,l1);
                    long i0 = (((long)bh*64 + col)   << 10) + l;
                    long i1 = (((long)bh*64 + col+1) << 10) + l;
                    Dh[i0] = h0; Dl[i0] = l0;
                    Dh[i1] = h1; Dl[i1] = l1;
                }
            }
    }
}

// =====================================================================
// K2: causal Toeplitz conv GEMM. C tile 128 l x 128 (kc|vc feat).
// =====================================================================
__global__ __launch_bounds__(256) void conv_mma(const float* __restrict__ sbasis)
{
    extern __shared__ char sm[];
    float* fsm = (float*)sm;                 // 4096 B
    char* bufs = sm + 4096;
    const uint32_t sb = smem_u32(bufs);
    const int tid = threadIdx.x;
    const int lane = tid & 31, wid = tid >> 5;
    const int warpM = wid & 3, warpN = wid >> 2;
    const int lt = blockIdx.x;
    const int bh = blockIdx.y;
    const int head = bh & 7;
    const int L0 = lt * 128;
    const int NC = 4 * (lt + 1);

    for (int i = tid; i < 1024; i += 256) fsm[i] = sbasis[i * 8 + head];
    __syncthreads();

    const __nv_bfloat16* kh = g_ktr_hi + (long)bh * 64 * 1024;
    const __nv_bfloat16* kl = g_ktr_lo + (long)bh * 64 * 1024;
    const __nv_bfloat16* vh = g_vtr_hi + (long)bh * 64 * 1024;
    const __nv_bfloat16* vl = g_vtr_lo + (long)bh * 64 * 1024;

    float acc[2][8][4] = {};

    // chunk generator+loader
    auto fill = [&](int c){
        char* tb = bufs + (c & 1) * BUF_B;
        int T0 = c * 32;
        int diff = L0 - T0;
        // Toeplitz A hi/lo
        for (int i = tid; i < 4096; i += 256){
            int r = i >> 5, cc = i & 31;
            int lag = diff + r - cc;
            float v = (lag >= 0) ? fsm[lag] : 0.0f;
            __nv_bfloat16 hv, lv; split_bf(v, hv, lv);
            int off = (r * LDAe + cc) * 2;
            *(__nv_bfloat16*)(tb + off) = hv;
            *(__nv_bfloat16*)(tb + TILE_B + off) = lv;
        }
        // B rows: 0-63 k, 64-127 v
        #pragma unroll
        for (int j = 0; j < 2; j++){
            int i = tid + j * 256;
            int r = i >> 2, seg = (i & 3) * 8;
            const __nv_bfloat16* sh = (r < 64) ? kh + ((long)r << 10) : vh + ((long)(r-64) << 10);
            const __nv_bfloat16* sl = (r < 64) ? kl + ((long)r << 10) : vl + ((long)(r-64) << 10);
            *(float4*)(tb + 2*TILE_B + (r * LDAe + seg) * 2) = *(const float4*)(sh + T0 + seg);
            *(float4*)(tb + 3*TILE_B + (r * LDAe + seg) * 2) = *(const float4*)(sl + T0 + seg);
        }
    };

    fill(0);
    __syncthreads();
    for (int c = 0; c < NC; c++){
        if (c + 1 < NC) fill(c + 1);
        uint32_t o = sb + (c & 1) * BUF_B;
        mma_chunk(o, o + TILE_B, o + 2*TILE_B, o + 3*TILE_B, warpM, warpN, lane, acc);
        __syncthreads();
    }

    // epilogue: fp32 kc/vc
    const int g = lane >> 2, tig = lane & 3;
    float* Dst = warpN ? g_vc : g_kc;
    #pragma unroll
    for (int mt = 0; mt < 2; mt++)
        #pragma unroll
        for (int nt = 0; nt < 8; nt++){
            int col = nt * 8 + tig * 2;
            #pragma unroll
            for (int rr = 0; rr < 2; rr++){
                int l = L0 + warpM*32 + mt*16 + g + rr*8;
                float2 o; o.x = acc[mt][nt][rr*2+0]; o.y = acc[mt][nt][rr*2+1];
                *(float2*)(Dst + (((long)bh << 10) + l) * 64 + col) = o;
            }
        }
}

// =====================================================================
// K3: gates
// =====================================================================
__global__ __launch_bounds__(256) void gate_kernel(
    const float* __restrict__ wg, const float* __restrict__ wgb)
{
    __shared__ float Wg[64][64];
    const int tid = threadIdx.x;
    for (int i = tid; i < 4096; i += 256) Wg[i >> 6][i & 63] = wg[i];
    __syncthreads();

    const int gidx = blockIdx.x * 256 + tid;
    const float4* k4 = (const float4*)(g_kc + (long)gidx * 64);
    const float4* v4 = (const float4*)(g_vc + (long)gidx * 64);
    float kreg[64], vreg[64];
    #pragma unroll
    for (int n = 0; n < 16; n++){
        float4 a = k4[n];
        kreg[n*4+0]=a.x; kreg[n*4+1]=a.y; kreg[n*4+2]=a.z; kreg[n*4+3]=a.w;
        float4 b = v4[n];
        vreg[n*4+0]=b.x; vreg[n*4+1]=b.y; vreg[n*4+2]=b.z; vreg[n*4+3]=b.w;
    }
    float acc = 0.0f;
    for (int m = 0; m < 64; m++){
        float dot = 0.0f;
        #pragma unroll
        for (int n = 0; n < 64; n++) dot += Wg[m][n] * kreg[n];
        acc += vreg[m] * dot;
    }
    acc += wgb[0];
    float rl = fmaxf(acc, 0.0f);
    g_gate[gidx] = rl * rl + EPSF;
}

// =====================================================================
// K4: scans
// =====================================================================
__device__ __forceinline__ void block_scan_1024(float* arr, float* wsum)
{
    const int tid = threadIdx.x;
    const int lane = tid & 31, wid = tid >> 5;
    float v0 = arr[tid*4+0], v1 = arr[tid*4+1], v2 = arr[tid*4+2], v3 = arr[tid*4+3];
    v1 += v0; v2 += v1; v3 += v2;
    float s = v3;
    #pragma unroll
    for (int o = 1; o < 32; o <<= 1) {
        float t = __shfl_up_sync(0xffffffff, s, o);
        if (lane >= o) s += t;
    }
    float excl = s - v3;
    if (lane == 31) wsum[wid] = s;
    __syncthreads();
    if (wid == 0) {
        float ws = (lane < 8) ? wsum[lane] : 0.0f;
        #pragma unroll
        for (int o = 1; o < 8; o <<= 1) {
            float t = __shfl_up_sync(0xffffffff, ws, o);
            if (lane >= o) ws += t;
        }
        if (lane < 8) wsum[lane] = ws;
    }
    __syncthreads();
    float base = ((wid > 0) ? wsum[wid - 1] : 0.0f) + excl;
    arr[tid*4+0] = v0 + base; arr[tid*4+1] = v1 + base;
    arr[tid*4+2] = v2 + base; arr[tid*4+3] = v3 + base;
    __syncthreads();
}

__global__ __launch_bounds__(256) void scan_kernel()
{
    __shared__ float g[1024];
    __shared__ float p[1024];
    __shared__ float r[1024];
    __shared__ float ws[8];
    const int bh = blockIdx.x;
    const int tid = threadIdx.x;
    const float* gin = g_gate + bh * 1024;
    for (int i = tid; i < 1024; i += 256) { float v = gin[i]; g[i] = v; p[i] = v; }
    __syncthreads();
    block_scan_1024(p, ws);
    for (int i = tid; i < 1024; i += 256) r[i] = 1.0f / (p[i] + EPSF);
    __syncthreads();
    for (int i = tid; i < 1024; i += 256) p[i] = r[i];
    __syncthreads();
    block_scan_1024(p, ws);
    float total = p[1023];
    for (int i = tid; i < 1024; i += 256) {
        float c = total - p[i] + r[i];
        g_w[bh * 1024 + i] = g[i] * c;
    }
}

// =====================================================================
// K5: S partials
// =====================================================================
__global__ __launch_bounds__(256) void Spart_kernel()
{
    __shared__ float Vs[64][68];
    __shared__ float Ks[64][68];
    const int tc = blockIdx.x, bh = blockIdx.y;
    const float* vin = g_vc + (long)bh * Ll * hh;
    const float* kin = g_kc + (long)bh * Ll * hh;
    const float* wt  = g_w  + bh * Ll;
    const int tid = threadIdx.x;
    const int tx = tid & 15, ty = tid >> 4;
    float acc[4][4] = {};

    for (int T0 = tc * 256; T0 < tc * 256 + 256; T0 += 64) {
        for (int i = tid; i < 64 * 16; i += 256) {
            int rrow = i >> 4, c = (i & 15) << 2;
            float w = wt[T0 + rrow];
            float4 vv = *(const float4*)(vin + (T0 + rrow) * 64 + c);
            vv.x *= w; vv.y *= w; vv.z *= w; vv.w *= w;
            *(float4*)&Vs[rrow][c] = vv;
            *(float4*)&Ks[rrow][c] = *(const float4*)(kin + (T0 + rrow) * 64 + c);
        }
        __syncthreads();
        #pragma unroll 4
        for (int tt = 0; tt < 64; tt++) {
            float4 a4 = *(const float4*)&Vs[tt][ty * 4];
            float4 b4 = *(const float4*)&Ks[tt][tx * 4];
            float aa[4] = {a4.x, a4.y, a4.z, a4.w};
            float bb[4] = {b4.x, b4.y, b4.z, b4.w};
            #pragma unroll
            for (int i = 0; i < 4; i++)
                #pragma unroll
                for (int j = 0; j < 4; j++)
                    acc[i][j] += aa[i] * bb[j];
        }
        __syncthreads();
    }
    float* dst = g_Spart + (tc * 16 + bh) * 4096;
    #pragma unroll
    for (int i = 0; i < 4; i++)
        #pragma unroll
        for (int j = 0; j < 4; j++)
            dst[(ty * 4 + i) * 64 + tx * 4 + j] = acc[i][j];
}

// =====================================================================
// K6: ctxt = q @ S, normalize, bf16 hi/lo unit
// =====================================================================
__global__ __launch_bounds__(256) void ctxt_kernel()
{
    __shared__ float Ss[64][65];
    const int b = blockIdx.z, head = blockIdx.y, lc = blockIdx.x;
    const int bh = b * Hh + head;
    const int tid = threadIdx.x;
    for (int i = tid; i < 4096; i += 256) {
        float s = 0.0f;
        #pragma unroll
        for (int p = 0; p < 4; p++) s += g_Spart[(p * 16 + bh) * 4096 + i];
        Ss[i >> 6][i & 63] = s;
    }
    __syncthreads();
    const int l = lc * 256 + tid;
    const float* qrow = g_q + ((long)bh * Ll + l) * hh;
    float out[64];
    #pragma unroll
    for (int e = 0; e < 64; e++) out[e] = 0.0f;
    for (int d = 0; d < 64; d++) {
        float qd = qrow[d];
        #pragma unroll
        for (int e = 0; e < 64; e++) out[e] += qd * Ss[d][e];
    }
    float nrm = 0.0f;
    #pragma unroll
    for (int e = 0; e < 64; e++) nrm += out[e] * out[e];
    float inv = 1.0f / fmaxf(sqrtf(nrm), EPSF);
    long off = ((long)(b * 1024 + l)) * 512 + head * 64;
    #pragma unroll
    for (int e = 0; e < 64; e += 2){
        float a = out[e] * inv, c = out[e+1] * inv;
        __nv_bfloat16 ah, al, ch, cl;
        split_bf(a, ah, al); split_bf(c, ch, cl);
        *(__nv_bfloat162*)(g_uhi + off + e) = __halves2bfloat162(ah, ch);
        *(__nv_bfloat162*)(g_ulo + off + e) = __halves2bfloat162(al, cl);
    }
}

// =====================================================================
// K7: output projection GEMM
// =====================================================================
__global__ __launch_bounds__(256) void out_mma(
    const float* __restrict__ bo, float* __restrict__ out)
{
    extern __shared__ char sm[];
    const uint32_t sb = smem_u32(sm);
    const int tid = threadIdx.x;
    const int lane = tid & 31, wid = tid >> 5;
    const int warpM = wid & 3, warpN = wid >> 2;
    const int row0 = blockIdx.y * 128;
    const int n0   = blockIdx.x * 128;

    float acc[2][8][4] = {};
    {
        char* tb = sm;
        load_tile(tb,            g_uhi + (long)row0*512, 512, tid);
        load_tile(tb +   TILE_B, g_ulo + (long)row0*512, 512, tid);
        load_tile(tb + 2*TILE_B, g_woT_hi + (long)n0*512, 512, tid);
        load_tile(tb + 3*TILE_B, g_woT_lo + (long)n0*512, 512, tid);
    }
    __syncthreads();
    for (int c = 0; c < 16; c++){
        if (c + 1 < 16){
            char* tb = sm + ((c + 1) & 1) * BUF_B;
            int k0 = (c + 1) * 32;
            load_tile(tb,            g_uhi + (long)row0*512 + k0, 512, tid);
            load_tile(tb +   TILE_B, g_ulo + (long)row0*512 + k0, 512, tid);
            load_tile(tb + 2*TILE_B, g_woT_hi + (long)n0*512 + k0, 512, tid);
            load_tile(tb + 3*TILE_B, g_woT_lo + (long)n0*512 + k0, 512, tid);
        }
        uint32_t o = sb + (c & 1) * BUF_B;
        mma_chunk(o, o + TILE_B, o + 2*TILE_B, o + 3*TILE_B, warpM, warpN, lane, acc);
        __syncthreads();
    }

    const int g = lane >> 2, tig = lane & 3;
    #pragma unroll
    for (int mt = 0; mt < 2; mt++)
        #pragma unroll
        for (int nt = 0; nt < 8; nt++){
            int col = n0 + warpN*64 + nt*8 + tig*2;
            float b0 = bo[col], b1 = bo[col+1];
            #pragma unroll
            for (int rr = 0; rr < 2; rr++){
                int row = row0 + warpM*32 + mt*16 + g + rr*8;
                float2 o; o.x = acc[mt][nt][rr*2+0] + b0; o.y = acc[mt][nt][rr*2+1] + b1;
                *(float2*)(out + (long)row * 512 + col) = o;
            }
        }
}

// =====================================================================
extern "C" void kernel_launch(void* const* d_in, const int* in_sizes, int n_in,
                              void* d_out, int out_size)
{
    const float* x   = (const float*)d_in[0];
    const float* sb  = (const float*)d_in[1];
    const float* wq  = (const float*)d_in[2];
    const float* bq  = (const float*)d_in[3];
    const float* wk  = (const float*)d_in[4];
    const float* bk  = (const float*)d_in[5];
    const float* wv  = (const float*)d_in[6];
    const float* bv  = (const float*)d_in[7];
    const float* wo  = (const float*)d_in[8];
    const float* bo  = (const float*)d_in[9];
    const float* wg  = (const float*)d_in[10];
    const float* wgb = (const float*)d_in[11];
    float* out = (float*)d_out;

    const int GEMM_SMEM = 2 * BUF_B;          // 81920
    const int CONV_SMEM = 4096 + 2 * BUF_B;   // 86016

    cudaFuncSetAttribute(proj_mma, cudaFuncAttributeMaxDynamicSharedMemorySize, GEMM_SMEM);
    cudaFuncSetAttribute(conv_mma, cudaFuncAttributeMaxDynamicSharedMemorySize, CONV_SMEM);
    cudaFuncSetAttribute(out_mma,  cudaFuncAttributeMaxDynamicSharedMemorySize, GEMM_SMEM);

    prep_x<<<1024, 256>>>(x);
    prep_w<<<dim3(32, 8), 256>>>(wq, wk, wv, wo);
    proj_mma<<<dim3(12, 16), 256, GEMM_SMEM>>>(bq, bk, bv);
    conv_mma<<<dim3(8, 16), 256, CONV_SMEM>>>(sb);
    gate_kernel<<<64, 256>>>(wg, wgb);
    scan_kernel<<<16, 256>>>();
    Spart_kernel<<<dim3(4, 16), 256>>>();
    ctxt_kernel<<<dim3(4, 8, 2), 256>>>();
    out_mma<<<dim3(4, 16), 256, GEMM_SMEM>>>(bo, out);
}

// round 4
// speedup vs baseline: 1.6326x; 1.1724x over previous
#include <cuda_runtime.h>
#include <cuda_bf16.h>
#include <cstdint>
#include <math.h>

#define Bb 2
#define Ll 1024
#define Dd 512
#define Hh 8
#define hh 64
#define EPSF 1e-5f

// ---------------- scratch (device globals; no runtime allocation) ----------------
__device__ __nv_bfloat16 g_xhi[2048*512], g_xlo[2048*512];
__device__ __nv_bfloat16 g_wqkvT_hi[1536*512], g_wqkvT_lo[1536*512];
__device__ __nv_bfloat16 g_woT_hi[512*512],  g_woT_lo[512*512];
__device__ __nv_bfloat16 g_ktr_hi[16*64*1024], g_ktr_lo[16*64*1024];
__device__ __nv_bfloat16 g_vtr_hi[16*64*1024], g_vtr_lo[16*64*1024];
__device__ __nv_bfloat16 g_uhi[2048*512], g_ulo[2048*512];
// precomputed Toeplitz tiles: [head][diff_idx][64*40] padded, hi/lo
__device__ __nv_bfloat16 g_toep_hi[8*32*2560], g_toep_lo[8*32*2560];
__device__ float g_q [16*1024*64];
__device__ float g_kc[16*1024*64];
__device__ float g_vc[16*1024*64];
__device__ float g_gate[16*1024];
__device__ float g_w   [16*1024];
__device__ float g_Spart[8*16*64*64];

// ---------------- helpers ----------------
__device__ __forceinline__ uint32_t smem_u32(const void* p){
    uint32_t a;
    asm("{ .reg .u64 t; cvta.to.shared.u64 t, %1; cvt.u32.u64 %0, t; }" : "=r"(a) : "l"(p));
    return a;
}

#define LDSM_X4(d0,d1,d2,d3,addr) \
    asm volatile("ldmatrix.sync.aligned.m8n8.x4.shared.b16 {%0,%1,%2,%3}, [%4];" \
        : "=r"(d0),"=r"(d1),"=r"(d2),"=r"(d3) : "r"(addr))

__device__ __forceinline__ void mma_bf16(float* c, const uint32_t* a, uint32_t b0, uint32_t b1){
    asm volatile(
        "mma.sync.aligned.m16n8k16.row.col.f32.bf16.bf16.f32 "
        "{%0,%1,%2,%3},{%4,%5,%6,%7},{%8,%9},{%0,%1,%2,%3};"
        : "+f"(c[0]),"+f"(c[1]),"+f"(c[2]),"+f"(c[3])
        : "r"(a[0]),"r"(a[1]),"r"(a[2]),"r"(a[3]),"r"(b0),"r"(b1));
}

__device__ __forceinline__ void split_bf(float v, __nv_bfloat16& h, __nv_bfloat16& l){
    h = __float2bfloat16(v);
    l = __float2bfloat16(v - __bfloat162float(h));
}

// smem tile geometry: rows padded to 40 bf16 (80B)
#define LDAe 40
#define TILE_B 10240              // 128 * 40 * 2
#define BUF_B  40960              // Ah | Al | Bh | Bl (128-row kernels)

// core: one 32-deep K chunk, 128M x 128N (warp tile 32x64). acc[2][8][4].
__device__ __forceinline__ void mma_chunk(
    uint32_t Ah, uint32_t Al, uint32_t Bh, uint32_t Bl,
    int warpM, int warpN, int lane, float acc[2][8][4])
{
    const int rsub = ((lane >> 3) & 1) * 8 + (lane & 7);
    const int ksel = (lane >> 4) * 8;
    #pragma unroll
    for (int ks = 0; ks < 32; ks += 16){
        uint32_t ah[2][4], al[2][4], bh[4][4], bl[4][4];
        #pragma unroll
        for (int mt = 0; mt < 2; mt++){
            uint32_t off = ((warpM*32 + mt*16 + rsub) * LDAe + ks + ksel) * 2;
            LDSM_X4(ah[mt][0],ah[mt][1],ah[mt][2],ah[mt][3], Ah + off);
            LDSM_X4(al[mt][0],al[mt][1],al[mt][2],al[mt][3], Al + off);
        }
        #pragma unroll
        for (int np = 0; np < 4; np++){
            uint32_t off = ((warpN*64 + np*16 + rsub) * LDAe + ks + ksel) * 2;
            LDSM_X4(bh[np][0],bh[np][1],bh[np][2],bh[np][3], Bh + off);
            LDSM_X4(bl[np][0],bl[np][1],bl[np][2],bl[np][3], Bl + off);
        }
        #pragma unroll
        for (int mt = 0; mt < 2; mt++)
            #pragma unroll
            for (int nt = 0; nt < 8; nt++){
                int np = nt >> 1, s = nt & 1;
                uint32_t b0h = bh[np][s], b1h = bh[np][s+2];
                uint32_t b0l = bl[np][s], b1l = bl[np][s+2];
                mma_bf16(acc[mt][nt], ah[mt], b0h, b1h);
                mma_bf16(acc[mt][nt], al[mt], b0h, b1h);
                mma_bf16(acc[mt][nt], ah[mt], b0l, b1l);
            }
    }
}

// conv variant: 64M x 128N (warp tile 32x32). acc[2][4][4].
__device__ __forceinline__ void mma_chunk64(
    uint32_t Ah, uint32_t Al, uint32_t Bh, uint32_t Bl,
    int warpM, int warpN, int lane, float acc[2][4][4])
{
    const int rsub = ((lane >> 3) & 1) * 8 + (lane & 7);
    const int ksel = (lane >> 4) * 8;
    #pragma unroll
    for (int ks = 0; ks < 32; ks += 16){
        uint32_t ah[2][4], al[2][4], bh[2][4], bl[2][4];
        #pragma unroll
        for (int mt = 0; mt < 2; mt++){
            uint32_t off = ((warpM*32 + mt*16 + rsub) * LDAe + ks + ksel) * 2;
            LDSM_X4(ah[mt][0],ah[mt][1],ah[mt][2],ah[mt][3], Ah + off);
            LDSM_X4(al[mt][0],al[mt][1],al[mt][2],al[mt][3], Al + off);
        }
        #pragma unroll
        for (int np = 0; np < 2; np++){
            uint32_t off = ((warpN*32 + np*16 + rsub) * LDAe + ks + ksel) * 2;
            LDSM_X4(bh[np][0],bh[np][1],bh[np][2],bh[np][3], Bh + off);
            LDSM_X4(bl[np][0],bl[np][1],bl[np][2],bl[np][3], Bl + off);
        }
        #pragma unroll
        for (int mt = 0; mt < 2; mt++)
            #pragma unroll
            for (int nt = 0; nt < 4; nt++){
                int np = nt >> 1, s = nt & 1;
                uint32_t b0h = bh[np][s], b1h = bh[np][s+2];
                uint32_t b0l = bl[np][s], b1l = bl[np][s+2];
                mma_bf16(acc[mt][nt], ah[mt], b0h, b1h);
                mma_bf16(acc[mt][nt], al[mt], b0h, b1h);
                mma_bf16(acc[mt][nt], ah[mt], b0l, b1l);
            }
    }
}

// load one 128x32 bf16 tile (row-major src, stride elems) into padded smem
__device__ __forceinline__ void load_tile(char* dst, const __nv_bfloat16* src, int stride, int tid){
    #pragma unroll
    for (int j = 0; j < 2; j++){
        int i = tid + j * 256;
        int r = i >> 2, seg = (i & 3) * 8;
        float4 v = *(const float4*)(src + (long)r * stride + seg);
        *(float4*)(dst + (r * LDAe + seg) * 2) = v;
    }
}

// =====================================================================
// P1: x -> bf16 hi/lo
// =====================================================================
__global__ __launch_bounds__(256) void prep_x(const float* __restrict__ x)
{
    int i = blockIdx.x * 256 + threadIdx.x;
    float4 v = ((const float4*)x)[i];
    __nv_bfloat16 h0,l0,h1,l1,h2,l2,h3,l3;
    split_bf(v.x,h0,l0); split_bf(v.y,h1,l1); split_bf(v.z,h2,l2); split_bf(v.w,h3,l3);
    ((__nv_bfloat162*)g_xhi)[i*2+0] = __halves2bfloat162(h0,h1);
    ((__nv_bfloat162*)g_xhi)[i*2+1] = __halves2bfloat162(h2,h3);
    ((__nv_bfloat162*)g_xlo)[i*2+0] = __halves2bfloat162(l0,l1);
    ((__nv_bfloat162*)g_xlo)[i*2+1] = __halves2bfloat162(l2,l3);
}

// =====================================================================
// P2: transpose+convert weights
// =====================================================================
__global__ __launch_bounds__(256) void prep_w(
    const float* __restrict__ wq, const float* __restrict__ wk,
    const float* __restrict__ wv, const float* __restrict__ wo)
{
    __shared__ float s[64][65];
    int bx = blockIdx.x;
    int k0 = blockIdx.y * 64;
    const float* W; __nv_bfloat16 *Dh, *Dl; int n0; int dstRow0;
    if (bx < 24) {
        int ng0 = bx * 64; int mat = ng0 >> 9;
        W = (mat == 0) ? wq : (mat == 1) ? wk : wv;
        n0 = ng0 & 511; dstRow0 = ng0;
        Dh = g_wqkvT_hi; Dl = g_wqkvT_lo;
    } else {
        W = wo; n0 = (bx - 24) * 64; dstRow0 = n0;
        Dh = g_woT_hi; Dl = g_woT_lo;
    }
    int tid = threadIdx.x;
    #pragma unroll
    for (int i = 0; i < 4; i++){
        int r = i * 16 + (tid >> 4);
        int c = (tid & 15) * 4;
        float4 v = *(const float4*)(W + (k0 + r) * 512 + n0 + c);
        s[r][c+0]=v.x; s[r][c+1]=v.y; s[r][c+2]=v.z; s[r][c+3]=v.w;
    }
    __syncthreads();
    #pragma unroll
    for (int i = 0; i < 4; i++){
        int rn = i * 16 + (tid >> 4);
        int ck = (tid & 15) * 4;
        __nv_bfloat16 h[4], l[4];
        #pragma unroll
        for (int j = 0; j < 4; j++) split_bf(s[ck + j][rn], h[j], l[j]);
        int off = (dstRow0 + rn) * 512 + k0 + ck;
        *(__nv_bfloat162*)(Dh + off)     = __halves2bfloat162(h[0], h[1]);
        *(__nv_bfloat162*)(Dh + off + 2) = __halves2bfloat162(h[2], h[3]);
        *(__nv_bfloat162*)(Dl + off)     = __halves2bfloat162(l[0], l[1]);
        *(__nv_bfloat162*)(Dl + off + 2) = __halves2bfloat162(l[2], l[3]);
    }
}

// =====================================================================
// P3: precompute Toeplitz tiles (64 rows x 32 cols, padded LDAe), hi/lo.
// diff = diff_idx*32 - 32; entry[r][cc] = f[diff + r - cc] (0 if lag<0).
// =====================================================================
__global__ __launch_bounds__(256) void prep_toep(const float* __restrict__ sbasis)
{
    const int didx = blockIdx.x;      // 0..31
    const int head = blockIdx.y;      // 0..7
    const int diff = didx * 32 - 32;
    __nv_bfloat16* th = g_toep_hi + (head * 32 + didx) * 2560;
    __nv_bfloat16* tl = g_toep_lo + (head * 32 + didx) * 2560;
    for (int i = threadIdx.x; i < 64 * 32; i += 256){
        int r = i >> 5, cc = i & 31;
        int lag = diff + r - cc;
        float v = (lag >= 0 && lag < 1024) ? sbasis[lag * 8 + head] : 0.0f;
        __nv_bfloat16 hv, lv; split_bf(v, hv, lv);
        th[r * LDAe + cc] = hv;
        tl[r * LDAe + cc] = lv;
    }
}

// =====================================================================
// K1: QKV projection GEMM (bf16x3 mma.sync). C tile 128 tok x 128 feat.
// =====================================================================
__global__ __launch_bounds__(256) void proj_mma(
    const float* __restrict__ bq, const float* __restrict__ bk, const float* __restrict__ bv)
{
    extern __shared__ char sm[];
    const uint32_t sb = smem_u32(sm);
    const int tid = threadIdx.x;
    const int lane = tid & 31, wid = tid >> 5;
    const int warpM = wid & 3, warpN = wid >> 2;
    const int row0 = blockIdx.y * 128;
    const int n0   = blockIdx.x * 128;

    float acc[2][8][4] = {};

    {
        char* tb = sm;
        load_tile(tb,            g_xhi + (long)row0*512, 512, tid);
        load_tile(tb +   TILE_B, g_xlo + (long)row0*512, 512, tid);
        load_tile(tb + 2*TILE_B, g_wqkvT_hi + (long)n0*512, 512, tid);
        load_tile(tb + 3*TILE_B, g_wqkvT_lo + (long)n0*512, 512, tid);
    }
    __syncthreads();
    for (int c = 0; c < 16; c++){
        if (c + 1 < 16){
            char* tb = sm + ((c + 1) & 1) * BUF_B;
            int k0 = (c + 1) * 32;
            load_tile(tb,            g_xhi + (long)row0*512 + k0, 512, tid);
            load_tile(tb +   TILE_B, g_xlo + (long)row0*512 + k0, 512, tid);
            load_tile(tb + 2*TILE_B, g_wqkvT_hi + (long)n0*512 + k0, 512, tid);
            load_tile(tb + 3*TILE_B, g_wqkvT_lo + (long)n0*512 + k0, 512, tid);
        }
        uint32_t o = sb + (c & 1) * BUF_B;
        mma_chunk(o, o + TILE_B, o + 2*TILE_B, o + 3*TILE_B, warpM, warpN, lane, acc);
        __syncthreads();
    }

    const int g   = lane >> 2;
    const int tig = lane & 3;
    const int nwarp = n0 + warpN * 64;
    const int mat  = nwarp >> 9;
    const int head = (nwarp >> 6) & 7;
    const int mrow = row0 + warpM * 32;

    if (mat == 0){
        #pragma unroll
        for (int mt = 0; mt < 2; mt++)
            #pragma unroll
            for (int nt = 0; nt < 8; nt++){
                int col = nt * 8 + tig * 2;
                float b0 = bq[(nwarp & 511) + col], b1 = bq[(nwarp & 511) + col + 1];
                #pragma unroll
                for (int rr = 0; rr < 2; rr++){
                    int row = mrow + mt*16 + g + rr*8;
                    int b = row >> 10, l = row & 1023;
                    float2 o; o.x = acc[mt][nt][rr*2+0] + b0; o.y = acc[mt][nt][rr*2+1] + b1;
                    *(float2*)(g_q + (((long)(b*8+head) << 10) + l) * 64 + col) = o;
                }
            }
    } else {
        const float sc = (mat == 1) ? 0.125f : 1.0f;
        const float* bias = (mat == 1) ? bk : bv;
        __nv_bfloat16* Dh = (mat == 1) ? g_ktr_hi : g_vtr_hi;
        __nv_bfloat16* Dl = (mat == 1) ? g_ktr_lo : g_vtr_lo;
        #pragma unroll
        for (int mt = 0; mt < 2; mt++)
            #pragma unroll
            for (int nt = 0; nt < 8; nt++){
                int col = nt * 8 + tig * 2;
                float b0 = bias[(nwarp & 511) + col], b1 = bias[(nwarp & 511) + col + 1];
                #pragma unroll
                for (int rr = 0; rr < 2; rr++){
                    int row = mrow + mt*16 + g + rr*8;
                    int b = row >> 10, l = row & 1023;
                    int bh = b * 8 + head;
                    float v0 = (acc[mt][nt][rr*2+0] + b0) * sc;
                    float v1 = (acc[mt][nt][rr*2+1] + b1) * sc;
                    __nv_bfloat16 h0,l0,h1,l1;
                    split_bf(v0,h0,l0); split_bf(v1,h1,l1);
                    long i0 = (((long)bh*64 + col)   << 10) + l;
                    long i1 = (((long)bh*64 + col+1) << 10) + l;
                    Dh[i0] = h0; Dl[i0] = l0;
                    Dh[i1] = h1; Dl[i1] = l1;
                }
            }
    }
}

// =====================================================================
// K2: causal Toeplitz conv GEMM, balanced. 64-row l-tiles paired (i, 15-i).
// C tile 64 l x 128 (kc|vc). A tiles precomputed in gmem.
// =====================================================================
#define ATILE_B 5120               // 64*40*2
#define BUFC_B  30720              // Ah | Al | Bh | Bl

__global__ __launch_bounds__(256) void conv_mma()
{
    extern __shared__ char sm[];
    const uint32_t sb = smem_u32(sm);
    const int tid = threadIdx.x;
    const int lane = tid & 31, wid = tid >> 5;
    const int warpM = wid & 1, warpN = wid >> 1;
    const int pair = blockIdx.x;     // 0..7
    const int bh   = blockIdx.y;     // 0..15
    const int head = bh & 7;

    const __nv_bfloat16* kh = g_ktr_hi + (long)bh * 64 * 1024;
    const __nv_bfloat16* kl = g_ktr_lo + (long)bh * 64 * 1024;
    const __nv_bfloat16* vh = g_vtr_hi + (long)bh * 64 * 1024;
    const __nv_bfloat16* vl = g_vtr_lo + (long)bh * 64 * 1024;

    #pragma unroll 1
    for (int s = 0; s < 2; s++){
        const int tile = s ? (15 - pair) : pair;
        const int L0 = tile * 64;
        const int NC = 2 * tile + 2;

        float acc[2][4][4] = {};

        auto fill = [&](int c){
            char* tb = sm + (c & 1) * BUFC_B;
            int T0 = c * 32;
            int didx = 2 * tile - c + 1;
            const __nv_bfloat16* th = g_toep_hi + (head * 32 + didx) * 2560;
            const __nv_bfloat16* tl = g_toep_lo + (head * 32 + didx) * 2560;
            {   // A: 64 rows x 32 -> 256 float4 per half, 1 per thread
                int r = tid >> 2, seg = (tid & 3) * 8;
                int off = r * LDAe + seg;
                *(float4*)(tb + off * 2)           = *(const float4*)(th + off);
                *(float4*)(tb + ATILE_B + off * 2) = *(const float4*)(tl + off);
            }
            #pragma unroll
            for (int j = 0; j < 2; j++){   // B: 128 rows x 32
                int i = tid + j * 256;
                int r = i >> 2, seg = (i & 3) * 8;
                const __nv_bfloat16* sh = (r < 64) ? kh + ((long)r << 10) : vh + ((long)(r - 64) << 10);
                const __nv_bfloat16* sl = (r < 64) ? kl + ((long)r << 10) : vl + ((long)(r - 64) << 10);
                *(float4*)(tb + 2*ATILE_B + (r * LDAe + seg) * 2) = *(const float4*)(sh + T0 + seg);
                *(float4*)(tb + 2*ATILE_B + TILE_B + (r * LDAe + seg) * 2) = *(const float4*)(sl + T0 + seg);
            }
        };

        fill(0);
        __syncthreads();
        for (int c = 0; c < NC; c++){
            if (c + 1 < NC) fill(c + 1);
            uint32_t o = sb + (c & 1) * BUFC_B;
            mma_chunk64(o, o + ATILE_B, o + 2*ATILE_B, o + 2*ATILE_B + TILE_B,
                        warpM, warpN, lane, acc);
            __syncthreads();
        }

        // epilogue
        const int g = lane >> 2, tig = lane & 3;
        #pragma unroll
        for (int mt = 0; mt < 2; mt++)
            #pragma unroll
            for (int nt = 0; nt < 4; nt++){
                int n = warpN * 32 + nt * 8 + tig * 2;
                float* Dst = (n < 64) ? g_kc : g_vc;
                int col = n & 63;
                #pragma unroll
                for (int rr = 0; rr < 2; rr++){
                    int l = L0 + warpM*32 + mt*16 + g + rr*8;
                    float2 o; o.x = acc[mt][nt][rr*2+0]; o.y = acc[mt][nt][rr*2+1];
                    *(float2*)(Dst + (((long)bh << 10) + l) * 64 + col) = o;
                }
            }
        __syncthreads();
    }
}

// =====================================================================
// K3: gates
// =====================================================================
__global__ __launch_bounds__(256) void gate_kernel(
    const float* __restrict__ wg, const float* __restrict__ wgb)
{
    __shared__ float Wg[64][64];
    const int tid = threadIdx.x;
    for (int i = tid; i < 4096; i += 256) Wg[i >> 6][i & 63] = wg[i];
    __syncthreads();

    const int gidx = blockIdx.x * 256 + tid;
    const float4* k4 = (const float4*)(g_kc + (long)gidx * 64);
    const float4* v4 = (const float4*)(g_vc + (long)gidx * 64);
    float kreg[64], vreg[64];
    #pragma unroll
    for (int n = 0; n < 16; n++){
        float4 a = k4[n];
        kreg[n*4+0]=a.x; kreg[n*4+1]=a.y; kreg[n*4+2]=a.z; kreg[n*4+3]=a.w;
        float4 b = v4[n];
        vreg[n*4+0]=b.x; vreg[n*4+1]=b.y; vreg[n*4+2]=b.z; vreg[n*4+3]=b.w;
    }
    float acc = 0.0f;
    for (int m = 0; m < 64; m++){
        float dot = 0.0f;
        #pragma unroll
        for (int n = 0; n < 64; n++) dot += Wg[m][n] * kreg[n];
        acc += vreg[m] * dot;
    }
    acc += wgb[0];
    float rl = fmaxf(acc, 0.0f);
    g_gate[gidx] = rl * rl + EPSF;
}

// =====================================================================
// K4: scans
// =====================================================================
__device__ __forceinline__ void block_scan_1024(float* arr, float* wsum)
{
    const int tid = threadIdx.x;
    const int lane = tid & 31, wid = tid >> 5;
    float v0 = arr[tid*4+0], v1 = arr[tid*4+1], v2 = arr[tid*4+2], v3 = arr[tid*4+3];
    v1 += v0; v2 += v1; v3 += v2;
    float s = v3;
    #pragma unroll
    for (int o = 1; o < 32; o <<= 1) {
        float t = __shfl_up_sync(0xffffffff, s, o);
        if (lane >= o) s += t;
    }
    float excl = s - v3;
    if (lane == 31) wsum[wid] = s;
    __syncthreads();
    if (wid == 0) {
        float ws = (lane < 8) ? wsum[lane] : 0.0f;
        #pragma unroll
        for (int o = 1; o < 8; o <<= 1) {
            float t = __shfl_up_sync(0xffffffff, ws, o);
            if (lane >= o) ws += t;
        }
        if (lane < 8) wsum[lane] = ws;
    }
    __syncthreads();
    float base = ((wid > 0) ? wsum[wid - 1] : 0.0f) + excl;
    arr[tid*4+0] = v0 + base; arr[tid*4+1] = v1 + base;
    arr[tid*4+2] = v2 + base; arr[tid*4+3] = v3 + base;
    __syncthreads();
}

__global__ __launch_bounds__(256) void scan_kernel()
{
    __shared__ float g[1024];
    __shared__ float p[1024];
    __shared__ float r[1024];
    __shared__ float ws[8];
    const int bh = blockIdx.x;
    const int tid = threadIdx.x;
    const float* gin = g_gate + bh * 1024;
    for (int i = tid; i < 1024; i += 256) { float v = gin[i]; g[i] = v; p[i] = v; }
    __syncthreads();
    block_scan_1024(p, ws);
    for (int i = tid; i < 1024; i += 256) r[i] = 1.0f / (p[i] + EPSF);
    __syncthreads();
    for (int i = tid; i < 1024; i += 256) p[i] = r[i];
    __syncthreads();
    block_scan_1024(p, ws);
    float total = p[1023];
    for (int i = tid; i < 1024; i += 256) {
        float c = total - p[i] + r[i];
        g_w[bh * 1024 + i] = g[i] * c;
    }
}

// =====================================================================
// K5: S partials (8 t-chunks of 128)
// =====================================================================
__global__ __launch_bounds__(256) void Spart_kernel()
{
    __shared__ float Vs[64][68];
    __shared__ float Ks[64][68];
    const int tc = blockIdx.x, bh = blockIdx.y;
    const float* vin = g_vc + (long)bh * Ll * hh;
    const float* kin = g_kc + (long)bh * Ll * hh;
    const float* wt  = g_w  + bh * Ll;
    const int tid = threadIdx.x;
    const int tx = tid & 15, ty = tid >> 4;
    float acc[4][4] = {};

    for (int T0 = tc * 128; T0 < tc * 128 + 128; T0 += 64) {
        for (int i = tid; i < 64 * 16; i += 256) {
            int rrow = i >> 4, c = (i & 15) << 2;
            float w = wt[T0 + rrow];
            float4 vv = *(const float4*)(vin + (T0 + rrow) * 64 + c);
            vv.x *= w; vv.y *= w; vv.z *= w; vv.w *= w;
            *(float4*)&Vs[rrow][c] = vv;
            *(float4*)&Ks[rrow][c] = *(const float4*)(kin + (T0 + rrow) * 64 + c);
        }
        __syncthreads();
        #pragma unroll 4
        for (int tt = 0; tt < 64; tt++) {
            float4 a4 = *(const float4*)&Vs[tt][ty * 4];
            float4 b4 = *(const float4*)&Ks[tt][tx * 4];
            float aa[4] = {a4.x, a4.y, a4.z, a4.w};
            float bb[4] = {b4.x, b4.y, b4.z, b4.w};
            #pragma unroll
            for (int i = 0; i < 4; i++)
                #pragma unroll
                for (int j = 0; j < 4; j++)
                    acc[i][j] += aa[i] * bb[j];
        }
        __syncthreads();
    }
    float* dst = g_Spart + (tc * 16 + bh) * 4096;
    #pragma unroll
    for (int i = 0; i < 4; i++)
        #pragma unroll
        for (int j = 0; j < 4; j++)
            dst[(ty * 4 + i) * 64 + tx * 4 + j] = acc[i][j];
}

// =====================================================================
// K6: ctxt = q @ S, normalize, bf16 hi/lo unit
// =====================================================================
__global__ __launch_bounds__(256) void ctxt_kernel()
{
    __shared__ float Ss[64][65];
    const int b = blockIdx.z, head = blockIdx.y, lc = blockIdx.x;
    const int bh = b * Hh + head;
    const int tid = threadIdx.x;
    for (int i = tid; i < 4096; i += 256) {
        float s = 0.0f;
        #pragma unroll
        for (int p = 0; p < 8; p++) s += g_Spart[(p * 16 + bh) * 4096 + i];
        Ss[i >> 6][i & 63] = s;
    }
    __syncthreads();
    const int l = lc * 256 + tid;
    const float* qrow = g_q + ((long)bh * Ll + l) * hh;
    float out[64];
    #pragma unroll
    for (int e = 0; e < 64; e++) out[e] = 0.0f;
    for (int d = 0; d < 64; d++) {
        float qd = qrow[d];
        #pragma unroll
        for (int e = 0; e < 64; e++) out[e] += qd * Ss[d][e];
    }
    float nrm = 0.0f;
    #pragma unroll
    for (int e = 0; e < 64; e++) nrm += out[e] * out[e];
    float inv = 1.0f / fmaxf(sqrtf(nrm), EPSF);
    long off = ((long)(b * 1024 + l)) * 512 + head * 64;
    #pragma unroll
    for (int e = 0; e < 64; e += 2){
        float a = out[e] * inv, c = out[e+1] * inv;
        __nv_bfloat16 ah, al, ch, cl;
        split_bf(a, ah, al); split_bf(c, ch, cl);
        *(__nv_bfloat162*)(g_uhi + off + e) = __halves2bfloat162(ah, ch);
        *(__nv_bfloat162*)(g_ulo + off + e) = __halves2bfloat162(al, cl);
    }
}

// =====================================================================
// K7: output projection GEMM
// =====================================================================
__global__ __launch_bounds__(256) void out_mma(
    const float* __restrict__ bo, float* __restrict__ out)
{
    extern __shared__ char sm[];
    const uint32_t sb = smem_u32(sm);
    const int tid = threadIdx.x;
    const int lane = tid & 31, wid = tid >> 5;
    const int warpM = wid & 3, warpN = wid >> 2;
    const int row0 = blockIdx.y * 128;
    const int n0   = blockIdx.x * 128;

    float acc[2][8][4] = {};
    {
        char* tb = sm;
        load_tile(tb,            g_uhi + (long)row0*512, 512, tid);
        load_tile(tb +   TILE_B, g_ulo + (long)row0*512, 512, tid);
        load_tile(tb + 2*TILE_B, g_woT_hi + (long)n0*512, 512, tid);
        load_tile(tb + 3*TILE_B, g_woT_lo + (long)n0*512, 512, tid);
    }
    __syncthreads();
    for (int c = 0; c < 16; c++){
        if (c + 1 < 16){
            char* tb = sm + ((c + 1) & 1) * BUF_B;
            int k0 = (c + 1) * 32;
            load_tile(tb,            g_uhi + (long)row0*512 + k0, 512, tid);
            load_tile(tb +   TILE_B, g_ulo + (long)row0*512 + k0, 512, tid);
            load_tile(tb + 2*TILE_B, g_woT_hi + (long)n0*512 + k0, 512, tid);
            load_tile(tb + 3*TILE_B, g_woT_lo + (long)n0*512 + k0, 512, tid);
        }
        uint32_t o = sb + (c & 1) * BUF_B;
        mma_chunk(o, o + TILE_B, o + 2*TILE_B, o + 3*TILE_B, warpM, warpN, lane, acc);
        __syncthreads();
    }

    const int g = lane >> 2, tig = lane & 3;
    #pragma unroll
    for (int mt = 0; mt < 2; mt++)
        #pragma unroll
        for (int nt = 0; nt < 8; nt++){
            int col = n0 + warpN*64 + nt*8 + tig*2;
            float b0 = bo[col], b1 = bo[col+1];
            #pragma unroll
            for (int rr = 0; rr < 2; rr++){
                int row = row0 + warpM*32 + mt*16 + g + rr*8;
                float2 o; o.x = acc[mt][nt][rr*2+0] + b0; o.y = acc[mt][nt][rr*2+1] + b1;
                *(float2*)(out + (long)row * 512 + col) = o;
            }
        }
}

// =====================================================================
extern "C" void kernel_launch(void* const* d_in, const int* in_sizes, int n_in,
                              void* d_out, int out_size)
{
    const float* x   = (const float*)d_in[0];
    const float* sb  = (const float*)d_in[1];
    const float* wq  = (const float*)d_in[2];
    const float* bq  = (const float*)d_in[3];
    const float* wk  = (const float*)d_in[4];
    const float* bk  = (const float*)d_in[5];
    const float* wv  = (const float*)d_in[6];
    const float* bv  = (const float*)d_in[7];
    const float* wo  = (const float*)d_in[8];
    const float* bo  = (const float*)d_in[9];
    const float* wg  = (const float*)d_in[10];
    const float* wgb = (const float*)d_in[11];
    float* out = (float*)d_out;

    const int GEMM_SMEM = 2 * BUF_B;          // 81920
    const int CONV_SMEM = 2 * BUFC_B;         // 61440

    cudaFuncSetAttribute(proj_mma, cudaFuncAttributeMaxDynamicSharedMemorySize, GEMM_SMEM);
    cudaFuncSetAttribute(conv_mma, cudaFuncAttributeMaxDynamicSharedMemorySize, CONV_SMEM);
    cudaFuncSetAttribute(out_mma,  cudaFuncAttributeMaxDynamicSharedMemorySize, GEMM_SMEM);

    prep_x<<<1024, 256>>>(x);
    prep_w<<<dim3(32, 8), 256>>>(wq, wk, wv, wo);
    prep_toep<<<dim3(32, 8), 256>>>(sb);
    proj_mma<<<dim3(12, 16), 256, GEMM_SMEM>>>(bq, bk, bv);
    conv_mma<<<dim3(8, 16), 256, CONV_SMEM>>>();
    gate_kernel<<<64, 256>>>(wg, wgb);
    scan_kernel<<<16, 256>>>();
    Spart_kernel<<<dim3(8, 16), 256>>>();
    ctxt_kernel<<<dim3(4, 8, 2), 256>>>();
    out_mma<<<dim3(4, 16), 256, GEMM_SMEM>>>(bo, out);
}

// round 5
// speedup vs baseline: 1.8448x; 1.1300x over previous
#include <cuda_runtime.h>
#include <cuda_bf16.h>
#include <cstdint>
#include <math.h>

#define Bb 2
#define Ll 1024
#define Dd 512
#define Hh 8
#define hh 64
#define EPSF 1e-5f

// ---------------- scratch (device globals; no runtime allocation) ----------------
__device__ __nv_bfloat16 g_xhi[2048*512], g_xlo[2048*512];
__device__ __nv_bfloat16 g_wqkvT_hi[1536*512], g_wqkvT_lo[1536*512];
__device__ __nv_bfloat16 g_woT_hi[512*512],  g_woT_lo[512*512];
__device__ __nv_bfloat16 g_ktr_hi[16*64*1024], g_ktr_lo[16*64*1024];
__device__ __nv_bfloat16 g_vtr_hi[16*64*1024], g_vtr_lo[16*64*1024];
__device__ __nv_bfloat16 g_uhi[2048*512], g_ulo[2048*512];
// precomputed Toeplitz tiles: [head][diff_idx][64*40] padded, hi/lo
__device__ __nv_bfloat16 g_toep_hi[8*32*2560], g_toep_lo[8*32*2560];
__device__ float g_q [16*1024*64];
__device__ float g_kc[16*1024*64];
__device__ float g_vc[16*1024*64];
__device__ float g_gate[16*1024];
__device__ float g_w   [16*1024];
__device__ float g_Spart[8*16*64*64];

// ---------------- helpers ----------------
__device__ __forceinline__ uint32_t smem_u32(const void* p){
    uint32_t a;
    asm("{ .reg .u64 t; cvta.to.shared.u64 t, %1; cvt.u32.u64 %0, t; }" : "=r"(a) : "l"(p));
    return a;
}

#define LDSM_X4(d0,d1,d2,d3,addr) \
    asm volatile("ldmatrix.sync.aligned.m8n8.x4.shared.b16 {%0,%1,%2,%3}, [%4];" \
        : "=r"(d0),"=r"(d1),"=r"(d2),"=r"(d3) : "r"(addr))

__device__ __forceinline__ void mma_bf16(float* c, const uint32_t* a, uint32_t b0, uint32_t b1){
    asm volatile(
        "mma.sync.aligned.m16n8k16.row.col.f32.bf16.bf16.f32 "
        "{%0,%1,%2,%3},{%4,%5,%6,%7},{%8,%9},{%0,%1,%2,%3};"
        : "+f"(c[0]),"+f"(c[1]),"+f"(c[2]),"+f"(c[3])
        : "r"(a[0]),"r"(a[1]),"r"(a[2]),"r"(a[3]),"r"(b0),"r"(b1));
}

__device__ __forceinline__ void split_bf(float v, __nv_bfloat16& h, __nv_bfloat16& l){
    h = __float2bfloat16(v);
    l = __float2bfloat16(v - __bfloat162float(h));
}

__device__ __forceinline__ void cp16(uint32_t dst, const void* src){
    asm volatile("cp.async.ca.shared.global [%0], [%1], 16;" :: "r"(dst), "l"(src));
}
#define CP_COMMIT() asm volatile("cp.async.commit_group;" ::: "memory")
#define CP_WAIT1()  asm volatile("cp.async.wait_group 1;" ::: "memory")
#define CP_WAIT0()  asm volatile("cp.async.wait_group 0;" ::: "memory")

// smem tile geometry: rows padded to 40 bf16 (80B)
#define LDAe 40
#define TILE_B 10240              // 128 * 40 * 2
#define BUF_B  40960              // Ah | Al | Bh | Bl (128-row kernels)

// core: one 32-deep K chunk, 128M x 128N (warp tile 32x64). acc[2][8][4].
__device__ __forceinline__ void mma_chunk(
    uint32_t Ah, uint32_t Al, uint32_t Bh, uint32_t Bl,
    int warpM, int warpN, int lane, float acc[2][8][4])
{
    const int rsub = ((lane >> 3) & 1) * 8 + (lane & 7);
    const int ksel = (lane >> 4) * 8;
    #pragma unroll
    for (int ks = 0; ks < 32; ks += 16){
        uint32_t ah[2][4], al[2][4], bh[4][4], bl[4][4];
        #pragma unroll
        for (int mt = 0; mt < 2; mt++){
            uint32_t off = ((warpM*32 + mt*16 + rsub) * LDAe + ks + ksel) * 2;
            LDSM_X4(ah[mt][0],ah[mt][1],ah[mt][2],ah[mt][3], Ah + off);
            LDSM_X4(al[mt][0],al[mt][1],al[mt][2],al[mt][3], Al + off);
        }
        #pragma unroll
        for (int np = 0; np < 4; np++){
            uint32_t off = ((warpN*64 + np*16 + rsub) * LDAe + ks + ksel) * 2;
            LDSM_X4(bh[np][0],bh[np][1],bh[np][2],bh[np][3], Bh + off);
            LDSM_X4(bl[np][0],bl[np][1],bl[np][2],bl[np][3], Bl + off);
        }
        #pragma unroll
        for (int mt = 0; mt < 2; mt++)
            #pragma unroll
            for (int nt = 0; nt < 8; nt++){
                int np = nt >> 1, s = nt & 1;
                uint32_t b0h = bh[np][s], b1h = bh[np][s+2];
                uint32_t b0l = bl[np][s], b1l = bl[np][s+2];
                mma_bf16(acc[mt][nt], ah[mt], b0h, b1h);
                mma_bf16(acc[mt][nt], al[mt], b0h, b1h);
                mma_bf16(acc[mt][nt], ah[mt], b0l, b1l);
            }
    }
}

// conv variant: 64M x 128N (warp tile 32x32). acc[2][4][4].
__device__ __forceinline__ void mma_chunk64(
    uint32_t Ah, uint32_t Al, uint32_t Bh, uint32_t Bl,
    int warpM, int warpN, int lane, float acc[2][4][4])
{
    const int rsub = ((lane >> 3) & 1) * 8 + (lane & 7);
    const int ksel = (lane >> 4) * 8;
    #pragma unroll
    for (int ks = 0; ks < 32; ks += 16){
        uint32_t ah[2][4], al[2][4], bh[2][4], bl[2][4];
        #pragma unroll
        for (int mt = 0; mt < 2; mt++){
            uint32_t off = ((warpM*32 + mt*16 + rsub) * LDAe + ks + ksel) * 2;
            LDSM_X4(ah[mt][0],ah[mt][1],ah[mt][2],ah[mt][3], Ah + off);
            LDSM_X4(al[mt][0],al[mt][1],al[mt][2],al[mt][3], Al + off);
        }
        #pragma unroll
        for (int np = 0; np < 2; np++){
            uint32_t off = ((warpN*32 + np*16 + rsub) * LDAe + ks + ksel) * 2;
            LDSM_X4(bh[np][0],bh[np][1],bh[np][2],bh[np][3], Bh + off);
            LDSM_X4(bl[np][0],bl[np][1],bl[np][2],bl[np][3], Bl + off);
        }
        #pragma unroll
        for (int mt = 0; mt < 2; mt++)
            #pragma unroll
            for (int nt = 0; nt < 4; nt++){
                int np = nt >> 1, s = nt & 1;
                uint32_t b0h = bh[np][s], b1h = bh[np][s+2];
                uint32_t b0l = bl[np][s], b1l = bl[np][s+2];
                mma_bf16(acc[mt][nt], ah[mt], b0h, b1h);
                mma_bf16(acc[mt][nt], al[mt], b0h, b1h);
                mma_bf16(acc[mt][nt], ah[mt], b0l, b1l);
            }
    }
}

// async-load one 128x32 bf16 tile (row-major src, stride elems) into padded smem
__device__ __forceinline__ void load_tile_async(uint32_t dst, const __nv_bfloat16* src, int stride, int tid){
    #pragma unroll
    for (int j = 0; j < 2; j++){
        int i = tid + j * 256;
        int r = i >> 2, seg = (i & 3) * 8;
        cp16(dst + (r * LDAe + seg) * 2, src + (long)r * stride + seg);
    }
}

// =====================================================================
// P1: x -> bf16 hi/lo
// =====================================================================
__global__ __launch_bounds__(256) void prep_x(const float* __restrict__ x)
{
    int i = blockIdx.x * 256 + threadIdx.x;
    float4 v = ((const float4*)x)[i];
    __nv_bfloat16 h0,l0,h1,l1,h2,l2,h3,l3;
    split_bf(v.x,h0,l0); split_bf(v.y,h1,l1); split_bf(v.z,h2,l2); split_bf(v.w,h3,l3);
    ((__nv_bfloat162*)g_xhi)[i*2+0] = __halves2bfloat162(h0,h1);
    ((__nv_bfloat162*)g_xhi)[i*2+1] = __halves2bfloat162(h2,h3);
    ((__nv_bfloat162*)g_xlo)[i*2+0] = __halves2bfloat162(l0,l1);
    ((__nv_bfloat162*)g_xlo)[i*2+1] = __halves2bfloat162(l2,l3);
}

// =====================================================================
// P2: transpose+convert weights
// =====================================================================
__global__ __launch_bounds__(256) void prep_w(
    const float* __restrict__ wq, const float* __restrict__ wk,
    const float* __restrict__ wv, const float* __restrict__ wo)
{
    __shared__ float s[64][65];
    int bx = blockIdx.x;
    int k0 = blockIdx.y * 64;
    const float* W; __nv_bfloat16 *Dh, *Dl; int n0; int dstRow0;
    if (bx < 24) {
        int ng0 = bx * 64; int mat = ng0 >> 9;
        W = (mat == 0) ? wq : (mat == 1) ? wk : wv;
        n0 = ng0 & 511; dstRow0 = ng0;
        Dh = g_wqkvT_hi; Dl = g_wqkvT_lo;
    } else {
        W = wo; n0 = (bx - 24) * 64; dstRow0 = n0;
        Dh = g_woT_hi; Dl = g_woT_lo;
    }
    int tid = threadIdx.x;
    #pragma unroll
    for (int i = 0; i < 4; i++){
        int r = i * 16 + (tid >> 4);
        int c = (tid & 15) * 4;
        float4 v = *(const float4*)(W + (k0 + r) * 512 + n0 + c);
        s[r][c+0]=v.x; s[r][c+1]=v.y; s[r][c+2]=v.z; s[r][c+3]=v.w;
    }
    __syncthreads();
    #pragma unroll
    for (int i = 0; i < 4; i++){
        int rn = i * 16 + (tid >> 4);
        int ck = (tid & 15) * 4;
        __nv_bfloat16 h[4], l[4];
        #pragma unroll
        for (int j = 0; j < 4; j++) split_bf(s[ck + j][rn], h[j], l[j]);
        int off = (dstRow0 + rn) * 512 + k0 + ck;
        *(__nv_bfloat162*)(Dh + off)     = __halves2bfloat162(h[0], h[1]);
        *(__nv_bfloat162*)(Dh + off + 2) = __halves2bfloat162(h[2], h[3]);
        *(__nv_bfloat162*)(Dl + off)     = __halves2bfloat162(l[0], l[1]);
        *(__nv_bfloat162*)(Dl + off + 2) = __halves2bfloat162(l[2], l[3]);
    }
}

// =====================================================================
// P3: precompute Toeplitz tiles (64 rows x 32 cols, padded LDAe), hi/lo.
// =====================================================================
__global__ __launch_bounds__(256) void prep_toep(const float* __restrict__ sbasis)
{
    const int didx = blockIdx.x;      // 0..31
    const int head = blockIdx.y;      // 0..7
    const int diff = didx * 32 - 32;
    __nv_bfloat16* th = g_toep_hi + (head * 32 + didx) * 2560;
    __nv_bfloat16* tl = g_toep_lo + (head * 32 + didx) * 2560;
    for (int i = threadIdx.x; i < 64 * 32; i += 256){
        int r = i >> 5, cc = i & 31;
        int lag = diff + r - cc;
        float v = (lag >= 0 && lag < 1024) ? sbasis[lag * 8 + head] : 0.0f;
        __nv_bfloat16 hv, lv; split_bf(v, hv, lv);
        th[r * LDAe + cc] = hv;
        tl[r * LDAe + cc] = lv;
    }
}

// =====================================================================
// K1: QKV projection GEMM (bf16x3 mma.sync + cp.async). 128x128 C tile.
// =====================================================================
__global__ __launch_bounds__(256) void proj_mma(
    const float* __restrict__ bq, const float* __restrict__ bk, const float* __restrict__ bv)
{
    extern __shared__ char sm[];
    const uint32_t sb = smem_u32(sm);
    const int tid = threadIdx.x;
    const int lane = tid & 31, wid = tid >> 5;
    const int warpM = wid & 3, warpN = wid >> 2;
    const int row0 = blockIdx.y * 128;
    const int n0   = blockIdx.x * 128;

    float acc[2][8][4] = {};

    auto issue = [&](int c){
        uint32_t tb = sb + (c & 1) * BUF_B;
        int k0 = c * 32;
        load_tile_async(tb,            g_xhi + (long)row0*512 + k0, 512, tid);
        load_tile_async(tb +   TILE_B, g_xlo + (long)row0*512 + k0, 512, tid);
        load_tile_async(tb + 2*TILE_B, g_wqkvT_hi + (long)n0*512 + k0, 512, tid);
        load_tile_async(tb + 3*TILE_B, g_wqkvT_lo + (long)n0*512 + k0, 512, tid);
        CP_COMMIT();
    };

    issue(0);
    for (int c = 0; c < 16; c++){
        if (c + 1 < 16){ issue(c + 1); CP_WAIT1(); } else { CP_WAIT0(); }
        __syncthreads();
        uint32_t o = sb + (c & 1) * BUF_B;
        mma_chunk(o, o + TILE_B, o + 2*TILE_B, o + 3*TILE_B, warpM, warpN, lane, acc);
        __syncthreads();
    }

    const int g   = lane >> 2;
    const int tig = lane & 3;
    const int nwarp = n0 + warpN * 64;
    const int mat  = nwarp >> 9;
    const int head = (nwarp >> 6) & 7;
    const int mrow = row0 + warpM * 32;

    if (mat == 0){
        #pragma unroll
        for (int mt = 0; mt < 2; mt++)
            #pragma unroll
            for (int nt = 0; nt < 8; nt++){
                int col = nt * 8 + tig * 2;
                float b0 = bq[(nwarp & 511) + col], b1 = bq[(nwarp & 511) + col + 1];
                #pragma unroll
                for (int rr = 0; rr < 2; rr++){
                    int row = mrow + mt*16 + g + rr*8;
                    int b = row >> 10, l = row & 1023;
                    float2 o; o.x = acc[mt][nt][rr*2+0] + b0; o.y = acc[mt][nt][rr*2+1] + b1;
                    *(float2*)(g_q + (((long)(b*8+head) << 10) + l) * 64 + col) = o;
                }
            }
    } else {
        const float sc = (mat == 1) ? 0.125f : 1.0f;
        const float* bias = (mat == 1) ? bk : bv;
        __nv_bfloat16* Dh = (mat == 1) ? g_ktr_hi : g_vtr_hi;
        __nv_bfloat16* Dl = (mat == 1) ? g_ktr_lo : g_vtr_lo;
        #pragma unroll
        for (int mt = 0; mt < 2; mt++)
            #pragma unroll
            for (int nt = 0; nt < 8; nt++){
                int col = nt * 8 + tig * 2;
                float b0 = bias[(nwarp & 511) + col], b1 = bias[(nwarp & 511) + col + 1];
                #pragma unroll
                for (int rr = 0; rr < 2; rr++){
                    int row = mrow + mt*16 + g + rr*8;
                    int b = row >> 10, l = row & 1023;
                    int bh = b * 8 + head;
                    float v0 = (acc[mt][nt][rr*2+0] + b0) * sc;
                    float v1 = (acc[mt][nt][rr*2+1] + b1) * sc;
                    __nv_bfloat16 h0,l0,h1,l1;
                    split_bf(v0,h0,l0); split_bf(v1,h1,l1);
                    long i0 = (((long)bh*64 + col)   << 10) + l;
                    long i1 = (((long)bh*64 + col+1) << 10) + l;
                    Dh[i0] = h0; Dl[i0] = l0;
                    Dh[i1] = h1; Dl[i1] = l1;
                }
            }
    }
}

// =====================================================================
// K2: causal Toeplitz conv GEMM, balanced + cp.async.
// =====================================================================
#define ATILE_B 5120               // 64*40*2
#define BUFC_B  30720              // Ah | Al | Bh | Bl

__global__ __launch_bounds__(256) void conv_mma()
{
    extern __shared__ char sm[];
    const uint32_t sb = smem_u32(sm);
    const int tid = threadIdx.x;
    const int lane = tid & 31, wid = tid >> 5;
    const int warpM = wid & 1, warpN = wid >> 1;
    const int pair = blockIdx.x;     // 0..7
    const int bh   = blockIdx.y;     // 0..15
    const int head = bh & 7;

    const __nv_bfloat16* kh = g_ktr_hi + (long)bh * 64 * 1024;
    const __nv_bfloat16* kl = g_ktr_lo + (long)bh * 64 * 1024;
    const __nv_bfloat16* vh = g_vtr_hi + (long)bh * 64 * 1024;
    const __nv_bfloat16* vl = g_vtr_lo + (long)bh * 64 * 1024;

    #pragma unroll 1
    for (int s = 0; s < 2; s++){
        const int tile = s ? (15 - pair) : pair;
        const int L0 = tile * 64;
        const int NC = 2 * tile + 2;

        float acc[2][4][4] = {};

        auto issue = [&](int c){
            uint32_t tb = sb + (c & 1) * BUFC_B;
            int T0 = c * 32;
            int didx = 2 * tile - c + 1;
            const __nv_bfloat16* th = g_toep_hi + (head * 32 + didx) * 2560;
            const __nv_bfloat16* tl = g_toep_lo + (head * 32 + didx) * 2560;
            {   // A halves: 1 cp16 per thread each
                int r = tid >> 2, seg = (tid & 3) * 8;
                int off = r * LDAe + seg;
                cp16(tb + off * 2, th + off);
                cp16(tb + ATILE_B + off * 2, tl + off);
            }
            #pragma unroll
            for (int j = 0; j < 2; j++){   // B: 128 rows x 32
                int i = tid + j * 256;
                int r = i >> 2, seg = (i & 3) * 8;
                const __nv_bfloat16* sh = (r < 64) ? kh + ((long)r << 10) : vh + ((long)(r - 64) << 10);
                const __nv_bfloat16* sl = (r < 64) ? kl + ((long)r << 10) : vl + ((long)(r - 64) << 10);
                cp16(tb + 2*ATILE_B + (r * LDAe + seg) * 2, sh + T0 + seg);
                cp16(tb + 2*ATILE_B + TILE_B + (r * LDAe + seg) * 2, sl + T0 + seg);
            }
            CP_COMMIT();
        };

        issue(0);
        for (int c = 0; c < NC; c++){
            if (c + 1 < NC){ issue(c + 1); CP_WAIT1(); } else { CP_WAIT0(); }
            __syncthreads();
            uint32_t o = sb + (c & 1) * BUFC_B;
            mma_chunk64(o, o + ATILE_B, o + 2*ATILE_B, o + 2*ATILE_B + TILE_B,
                        warpM, warpN, lane, acc);
            __syncthreads();
        }

        const int g = lane >> 2, tig = lane & 3;
        #pragma unroll
        for (int mt = 0; mt < 2; mt++)
            #pragma unroll
            for (int nt = 0; nt < 4; nt++){
                int n = warpN * 32 + nt * 8 + tig * 2;
                float* Dst = (n < 64) ? g_kc : g_vc;
                int col = n & 63;
                #pragma unroll
                for (int rr = 0; rr < 2; rr++){
                    int l = L0 + warpM*32 + mt*16 + g + rr*8;
                    float2 o; o.x = acc[mt][nt][rr*2+0]; o.y = acc[mt][nt][rr*2+1];
                    *(float2*)(Dst + (((long)bh << 10) + l) * 64 + col) = o;
                }
            }
        __syncthreads();
    }
}

// =====================================================================
// K3: gates
// =====================================================================
__global__ __launch_bounds__(256) void gate_kernel(
    const float* __restrict__ wg, const float* __restrict__ wgb)
{
    __shared__ float Wg[64][64];
    const int tid = threadIdx.x;
    for (int i = tid; i < 4096; i += 256) Wg[i >> 6][i & 63] = wg[i];
    __syncthreads();

    const int gidx = blockIdx.x * 256 + tid;
    const float4* k4 = (const float4*)(g_kc + (long)gidx * 64);
    const float4* v4 = (const float4*)(g_vc + (long)gidx * 64);
    float kreg[64], vreg[64];
    #pragma unroll
    for (int n = 0; n < 16; n++){
        float4 a = k4[n];
        kreg[n*4+0]=a.x; kreg[n*4+1]=a.y; kreg[n*4+2]=a.z; kreg[n*4+3]=a.w;
        float4 b = v4[n];
        vreg[n*4+0]=b.x; vreg[n*4+1]=b.y; vreg[n*4+2]=b.z; vreg[n*4+3]=b.w;
    }
    float acc = 0.0f;
    for (int m = 0; m < 64; m++){
        float dot = 0.0f;
        #pragma unroll
        for (int n = 0; n < 64; n++) dot += Wg[m][n] * kreg[n];
        acc += vreg[m] * dot;
    }
    acc += wgb[0];
    float rl = fmaxf(acc, 0.0f);
    g_gate[gidx] = rl * rl + EPSF;
}

// =====================================================================
// K4: scans
// =====================================================================
__device__ __forceinline__ void block_scan_1024(float* arr, float* wsum)
{
    const int tid = threadIdx.x;
    const int lane = tid & 31, wid = tid >> 5;
    float v0 = arr[tid*4+0], v1 = arr[tid*4+1], v2 = arr[tid*4+2], v3 = arr[tid*4+3];
    v1 += v0; v2 += v1; v3 += v2;
    float s = v3;
    #pragma unroll
    for (int o = 1; o < 32; o <<= 1) {
        float t = __shfl_up_sync(0xffffffff, s, o);
        if (lane >= o) s += t;
    }
    float excl = s - v3;
    if (lane == 31) wsum[wid] = s;
    __syncthreads();
    if (wid == 0) {
        float ws = (lane < 8) ? wsum[lane] : 0.0f;
        #pragma unroll
        for (int o = 1; o < 8; o <<= 1) {
            float t = __shfl_up_sync(0xffffffff, ws, o);
            if (lane >= o) ws += t;
        }
        if (lane < 8) wsum[lane] = ws;
    }
    __syncthreads();
    float base = ((wid > 0) ? wsum[wid - 1] : 0.0f) + excl;
    arr[tid*4+0] = v0 + base; arr[tid*4+1] = v1 + base;
    arr[tid*4+2] = v2 + base; arr[tid*4+3] = v3 + base;
    __syncthreads();
}

__global__ __launch_bounds__(256) void scan_kernel()
{
    __shared__ float g[1024];
    __shared__ float p[1024];
    __shared__ float r[1024];
    __shared__ float ws[8];
    const int bh = blockIdx.x;
    const int tid = threadIdx.x;
    const float* gin = g_gate + bh * 1024;
    for (int i = tid; i < 1024; i += 256) { float v = gin[i]; g[i] = v; p[i] = v; }
    __syncthreads();
    block_scan_1024(p, ws);
    for (int i = tid; i < 1024; i += 256) r[i] = 1.0f / (p[i] + EPSF);
    __syncthreads();
    for (int i = tid; i < 1024; i += 256) p[i] = r[i];
    __syncthreads();
    block_scan_1024(p, ws);
    float total = p[1023];
    for (int i = tid; i < 1024; i += 256) {
        float c = total - p[i] + r[i];
        g_w[bh * 1024 + i] = g[i] * c;
    }
}

// =====================================================================
// K5: S partials (8 t-chunks of 128)
// =====================================================================
__global__ __launch_bounds__(256) void Spart_kernel()
{
    __shared__ float Vs[64][68];
    __shared__ float Ks[64][68];
    const int tc = blockIdx.x, bh = blockIdx.y;
    const float* vin = g_vc + (long)bh * Ll * hh;
    const float* kin = g_kc + (long)bh * Ll * hh;
    const float* wt  = g_w  + bh * Ll;
    const int tid = threadIdx.x;
    const int tx = tid & 15, ty = tid >> 4;
    float acc[4][4] = {};

    for (int T0 = tc * 128; T0 < tc * 128 + 128; T0 += 64) {
        for (int i = tid; i < 64 * 16; i += 256) {
            int rrow = i >> 4, c = (i & 15) << 2;
            float w = wt[T0 + rrow];
            float4 vv = *(const float4*)(vin + (T0 + rrow) * 64 + c);
            vv.x *= w; vv.y *= w; vv.z *= w; vv.w *= w;
            *(float4*)&Vs[rrow][c] = vv;
            *(float4*)&Ks[rrow][c] = *(const float4*)(kin + (T0 + rrow) * 64 + c);
        }
        __syncthreads();
        #pragma unroll 4
        for (int tt = 0; tt < 64; tt++) {
            float4 a4 = *(const float4*)&Vs[tt][ty * 4];
            float4 b4 = *(const float4*)&Ks[tt][tx * 4];
            float aa[4] = {a4.x, a4.y, a4.z, a4.w};
            float bb[4] = {b4.x, b4.y, b4.z, b4.w};
            #pragma unroll
            for (int i = 0; i < 4; i++)
                #pragma unroll
                for (int j = 0; j < 4; j++)
                    acc[i][j] += aa[i] * bb[j];
        }
        __syncthreads();
    }
    float* dst = g_Spart + (tc * 16 + bh) * 4096;
    #pragma unroll
    for (int i = 0; i < 4; i++)
        #pragma unroll
        for (int j = 0; j < 4; j++)
            dst[(ty * 4 + i) * 64 + tx * 4 + j] = acc[i][j];
}

// =====================================================================
// K6: ctxt = q @ S, normalize, bf16 hi/lo unit
// =====================================================================
__global__ __launch_bounds__(256) void ctxt_kernel()
{
    __shared__ float Ss[64][65];
    const int b = blockIdx.z, head = blockIdx.y, lc = blockIdx.x;
    const int bh = b * Hh + head;
    const int tid = threadIdx.x;
    for (int i = tid; i < 4096; i += 256) {
        float s = 0.0f;
        #pragma unroll
        for (int p = 0; p < 8; p++) s += g_Spart[(p * 16 + bh) * 4096 + i];
        Ss[i >> 6][i & 63] = s;
    }
    __syncthreads();
    const int l = lc * 256 + tid;
    const float* qrow = g_q + ((long)bh * Ll + l) * hh;
    float out[64];
    #pragma unroll
    for (int e = 0; e < 64; e++) out[e] = 0.0f;
    for (int d = 0; d < 64; d++) {
        float qd = qrow[d];
        #pragma unroll
        for (int e = 0; e < 64; e++) out[e] += qd * Ss[d][e];
    }
    float nrm = 0.0f;
    #pragma unroll
    for (int e = 0; e < 64; e++) nrm += out[e] * out[e];
    float inv = 1.0f / fmaxf(sqrtf(nrm), EPSF);
    long off = ((long)(b * 1024 + l)) * 512 + head * 64;
    #pragma unroll
    for (int e = 0; e < 64; e += 2){
        float a = out[e] * inv, c = out[e+1] * inv;
        __nv_bfloat16 ah, al, ch, cl;
        split_bf(a, ah, al); split_bf(c, ch, cl);
        *(__nv_bfloat162*)(g_uhi + off + e) = __halves2bfloat162(ah, ch);
        *(__nv_bfloat162*)(g_ulo + off + e) = __halves2bfloat162(al, cl);
    }
}

// =====================================================================
// K7: output projection GEMM + cp.async
// =====================================================================
__global__ __launch_bounds__(256) void out_mma(
    const float* __restrict__ bo, float* __restrict__ out)
{
    extern __shared__ char sm[];
    const uint32_t sb = smem_u32(sm);
    const int tid = threadIdx.x;
    const int lane = tid & 31, wid = tid >> 5;
    const int warpM = wid & 3, warpN = wid >> 2;
    const int row0 = blockIdx.y * 128;
    const int n0   = blockIdx.x * 128;

    float acc[2][8][4] = {};

    auto issue = [&](int c){
        uint32_t tb = sb + (c & 1) * BUF_B;
        int k0 = c * 32;
        load_tile_async(tb,            g_uhi + (long)row0*512 + k0, 512, tid);
        load_tile_async(tb +   TILE_B, g_ulo + (long)row0*512 + k0, 512, tid);
        load_tile_async(tb + 2*TILE_B, g_woT_hi + (long)n0*512 + k0, 512, tid);
        load_tile_async(tb + 3*TILE_B, g_woT_lo + (long)n0*512 + k0, 512, tid);
        CP_COMMIT();
    };

    issue(0);
    for (int c = 0; c < 16; c++){
        if (c + 1 < 16){ issue(c + 1); CP_WAIT1(); } else { CP_WAIT0(); }
        __syncthreads();
        uint32_t o = sb + (c & 1) * BUF_B;
        mma_chunk(o, o + TILE_B, o + 2*TILE_B, o + 3*TILE_B, warpM, warpN, lane, acc);
        __syncthreads();
    }

    const int g = lane >> 2, tig = lane & 3;
    #pragma unroll
    for (int mt = 0; mt < 2; mt++)
        #pragma unroll
        for (int nt = 0; nt < 8; nt++){
            int col = n0 + warpN*64 + nt*8 + tig*2;
            float b0 = bo[col], b1 = bo[col+1];
            #pragma unroll
            for (int rr = 0; rr < 2; rr++){
                int row = row0 + warpM*32 + mt*16 + g + rr*8;
                float2 o; o.x = acc[mt][nt][rr*2+0] + b0; o.y = acc[mt][nt][rr*2+1] + b1;
                *(float2*)(out + (long)row * 512 + col) = o;
            }
        }
}

// =====================================================================
extern "C" void kernel_launch(void* const* d_in, const int* in_sizes, int n_in,
                              void* d_out, int out_size)
{
    const float* x   = (const float*)d_in[0];
    const float* sb  = (const float*)d_in[1];
    const float* wq  = (const float*)d_in[2];
    const float* bq  = (const float*)d_in[3];
    const float* wk  = (const float*)d_in[4];
    const float* bk  = (const float*)d_in[5];
    const float* wv  = (const float*)d_in[6];
    const float* bv  = (const float*)d_in[7];
    const float* wo  = (const float*)d_in[8];
    const float* bo  = (const float*)d_in[9];
    const float* wg  = (const float*)d_in[10];
    const float* wgb = (const float*)d_in[11];
    float* out = (float*)d_out;

    const int GEMM_SMEM = 2 * BUF_B;          // 81920
    const int CONV_SMEM = 2 * BUFC_B;         // 61440

    cudaFuncSetAttribute(proj_mma, cudaFuncAttributeMaxDynamicSharedMemorySize, GEMM_SMEM);
    cudaFuncSetAttribute(conv_mma, cudaFuncAttributeMaxDynamicSharedMemorySize, CONV_SMEM);
    cudaFuncSetAttribute(out_mma,  cudaFuncAttributeMaxDynamicSharedMemorySize, GEMM_SMEM);

    prep_x<<<1024, 256>>>(x);
    prep_w<<<dim3(32, 8), 256>>>(wq, wk, wv, wo);
    prep_toep<<<dim3(32, 8), 256>>>(sb);
    proj_mma<<<dim3(12, 16), 256, GEMM_SMEM>>>(bq, bk, bv);
    conv_mma<<<dim3(8, 16), 256, CONV_SMEM>>>();
    gate_kernel<<<64, 256>>>(wg, wgb);
    scan_kernel<<<16, 256>>>();
    Spart_kernel<<<dim3(8, 16), 256>>>();
    ctxt_kernel<<<dim3(4, 8, 2), 256>>>();
    out_mma<<<dim3(4, 16), 256, GEMM_SMEM>>>(bo, out);
}

// round 6
// speedup vs baseline: 1.8492x; 1.0024x over previous
#include <cuda_runtime.h>
#include <cuda_bf16.h>
#include <cstdint>
#include <math.h>

#define Bb 2
#define Ll 1024
#define Dd 512
#define Hh 8
#define hh 64
#define EPSF 1e-5f

// ---------------- scratch (device globals; no runtime allocation) ----------------
__device__ __nv_bfloat16 g_xhi[2048*512], g_xlo[2048*512];
__device__ __nv_bfloat16 g_wqkvT_hi[1536*512], g_wqkvT_lo[1536*512];
__device__ __nv_bfloat16 g_woT_hi[512*512],  g_woT_lo[512*512];
__device__ __nv_bfloat16 g_ktr_hi[16*64*1024], g_ktr_lo[16*64*1024];
__device__ __nv_bfloat16 g_vtr_hi[16*64*1024], g_vtr_lo[16*64*1024];
__device__ __nv_bfloat16 g_uhi[2048*512], g_ulo[2048*512];
// precomputed Toeplitz tiles: [head][diff_idx][64*40] padded, hi/lo
__device__ __nv_bfloat16 g_toep_hi[8*32*2560], g_toep_lo[8*32*2560];
__device__ float g_q [16*1024*64];
__device__ float g_kc[16*1024*64];
__device__ float g_vc[16*1024*64];
__device__ float g_gate[16*1024];
__device__ float g_w   [16*1024];
__device__ float g_Spart[8*16*64*64];

// ---------------- helpers ----------------
__device__ __forceinline__ uint32_t smem_u32(const void* p){
    uint32_t a;
    asm("{ .reg .u64 t; cvta.to.shared.u64 t, %1; cvt.u32.u64 %0, t; }" : "=r"(a) : "l"(p));
    return a;
}

#define LDSM_X4(d0,d1,d2,d3,addr) \
    asm volatile("ldmatrix.sync.aligned.m8n8.x4.shared.b16 {%0,%1,%2,%3}, [%4];" \
        : "=r"(d0),"=r"(d1),"=r"(d2),"=r"(d3) : "r"(addr))

__device__ __forceinline__ void mma_bf16(float* c, const uint32_t* a, uint32_t b0, uint32_t b1){
    asm volatile(
        "mma.sync.aligned.m16n8k16.row.col.f32.bf16.bf16.f32 "
        "{%0,%1,%2,%3},{%4,%5,%6,%7},{%8,%9},{%0,%1,%2,%3};"
        : "+f"(c[0]),"+f"(c[1]),"+f"(c[2]),"+f"(c[3])
        : "r"(a[0]),"r"(a[1]),"r"(a[2]),"r"(a[3]),"r"(b0),"r"(b1));
}

__device__ __forceinline__ void split_bf(float v, __nv_bfloat16& h, __nv_bfloat16& l){
    h = __float2bfloat16(v);
    l = __float2bfloat16(v - __bfloat162float(h));
}

__device__ __forceinline__ void cp16(uint32_t dst, const void* src){
    asm volatile("cp.async.ca.shared.global [%0], [%1], 16;" :: "r"(dst), "l"(src));
}
#define CP_COMMIT() asm volatile("cp.async.commit_group;" ::: "memory")
#define CP_WAIT1()  asm volatile("cp.async.wait_group 1;" ::: "memory")
#define CP_WAIT0()  asm volatile("cp.async.wait_group 0;" ::: "memory")

// smem tile geometry: rows padded to 40 bf16 (80B)
#define LDAe 40
#define TILE_B 10240              // 128 * 40 * 2
#define BUF_B  40960              // Ah | Al | Bh | Bl (128-row kernels)

// 4-warp variant: warp tile 64x64. acc[4][8][4].
__device__ __forceinline__ void mma_chunk_4w(
    uint32_t Ah, uint32_t Al, uint32_t Bh, uint32_t Bl,
    int warpM, int warpN, int lane, float acc[4][8][4])
{
    const int rsub = ((lane >> 3) & 1) * 8 + (lane & 7);
    const int ksel = (lane >> 4) * 8;
    #pragma unroll
    for (int ks = 0; ks < 32; ks += 16){
        uint32_t ah[4][4], al[4][4], bh[4][4], bl[4][4];
        #pragma unroll
        for (int mt = 0; mt < 4; mt++){
            uint32_t off = ((warpM*64 + mt*16 + rsub) * LDAe + ks + ksel) * 2;
            LDSM_X4(ah[mt][0],ah[mt][1],ah[mt][2],ah[mt][3], Ah + off);
            LDSM_X4(al[mt][0],al[mt][1],al[mt][2],al[mt][3], Al + off);
        }
        #pragma unroll
        for (int np = 0; np < 4; np++){
            uint32_t off = ((warpN*64 + np*16 + rsub) * LDAe + ks + ksel) * 2;
            LDSM_X4(bh[np][0],bh[np][1],bh[np][2],bh[np][3], Bh + off);
            LDSM_X4(bl[np][0],bl[np][1],bl[np][2],bl[np][3], Bl + off);
        }
        #pragma unroll
        for (int mt = 0; mt < 4; mt++)
            #pragma unroll
            for (int nt = 0; nt < 8; nt++){
                int np = nt >> 1, s = nt & 1;
                uint32_t b0h = bh[np][s], b1h = bh[np][s+2];
                uint32_t b0l = bl[np][s], b1l = bl[np][s+2];
                mma_bf16(acc[mt][nt], ah[mt], b0h, b1h);
                mma_bf16(acc[mt][nt], al[mt], b0h, b1h);
                mma_bf16(acc[mt][nt], ah[mt], b0l, b1l);
            }
    }
}

// 8-warp variant: warp tile 32x64. acc[2][8][4]. (used by out_mma)
__device__ __forceinline__ void mma_chunk(
    uint32_t Ah, uint32_t Al, uint32_t Bh, uint32_t Bl,
    int warpM, int warpN, int lane, float acc[2][8][4])
{
    const int rsub = ((lane >> 3) & 1) * 8 + (lane & 7);
    const int ksel = (lane >> 4) * 8;
    #pragma unroll
    for (int ks = 0; ks < 32; ks += 16){
        uint32_t ah[2][4], al[2][4], bh[4][4], bl[4][4];
        #pragma unroll
        for (int mt = 0; mt < 2; mt++){
            uint32_t off = ((warpM*32 + mt*16 + rsub) * LDAe + ks + ksel) * 2;
            LDSM_X4(ah[mt][0],ah[mt][1],ah[mt][2],ah[mt][3], Ah + off);
            LDSM_X4(al[mt][0],al[mt][1],al[mt][2],al[mt][3], Al + off);
        }
        #pragma unroll
        for (int np = 0; np < 4; np++){
            uint32_t off = ((warpN*64 + np*16 + rsub) * LDAe + ks + ksel) * 2;
            LDSM_X4(bh[np][0],bh[np][1],bh[np][2],bh[np][3], Bh + off);
            LDSM_X4(bl[np][0],bl[np][1],bl[np][2],bl[np][3], Bl + off);
        }
        #pragma unroll
        for (int mt = 0; mt < 2; mt++)
            #pragma unroll
            for (int nt = 0; nt < 8; nt++){
                int np = nt >> 1, s = nt & 1;
                uint32_t b0h = bh[np][s], b1h = bh[np][s+2];
                uint32_t b0l = bl[np][s], b1l = bl[np][s+2];
                mma_bf16(acc[mt][nt], ah[mt], b0h, b1h);
                mma_bf16(acc[mt][nt], al[mt], b0h, b1h);
                mma_bf16(acc[mt][nt], ah[mt], b0l, b1l);
            }
    }
}

// conv variant: 64M x 128N (warp tile 32x32). acc[2][4][4].
__device__ __forceinline__ void mma_chunk64(
    uint32_t Ah, uint32_t Al, uint32_t Bh, uint32_t Bl,
    int warpM, int warpN, int lane, float acc[2][4][4])
{
    const int rsub = ((lane >> 3) & 1) * 8 + (lane & 7);
    const int ksel = (lane >> 4) * 8;
    #pragma unroll
    for (int ks = 0; ks < 32; ks += 16){
        uint32_t ah[2][4], al[2][4], bh[2][4], bl[2][4];
        #pragma unroll
        for (int mt = 0; mt < 2; mt++){
            uint32_t off = ((warpM*32 + mt*16 + rsub) * LDAe + ks + ksel) * 2;
            LDSM_X4(ah[mt][0],ah[mt][1],ah[mt][2],ah[mt][3], Ah + off);
            LDSM_X4(al[mt][0],al[mt][1],al[mt][2],al[mt][3], Al + off);
        }
        #pragma unroll
        for (int np = 0; np < 2; np++){
            uint32_t off = ((warpN*32 + np*16 + rsub) * LDAe + ks + ksel) * 2;
            LDSM_X4(bh[np][0],bh[np][1],bh[np][2],bh[np][3], Bh + off);
            LDSM_X4(bl[np][0],bl[np][1],bl[np][2],bl[np][3], Bl + off);
        }
        #pragma unroll
        for (int mt = 0; mt < 2; mt++)
            #pragma unroll
            for (int nt = 0; nt < 4; nt++){
                int np = nt >> 1, s = nt & 1;
                uint32_t b0h = bh[np][s], b1h = bh[np][s+2];
                uint32_t b0l = bl[np][s], b1l = bl[np][s+2];
                mma_bf16(acc[mt][nt], ah[mt], b0h, b1h);
                mma_bf16(acc[mt][nt], al[mt], b0h, b1h);
                mma_bf16(acc[mt][nt], ah[mt], b0l, b1l);
            }
    }
}

// async-load one 128x32 bf16 tile into padded smem (256 threads)
__device__ __forceinline__ void load_tile_async(uint32_t dst, const __nv_bfloat16* src, int stride, int tid){
    #pragma unroll
    for (int j = 0; j < 2; j++){
        int i = tid + j * 256;
        int r = i >> 2, seg = (i & 3) * 8;
        cp16(dst + (r * LDAe + seg) * 2, src + (long)r * stride + seg);
    }
}
// 128-thread version
__device__ __forceinline__ void load_tile_async128(uint32_t dst, const __nv_bfloat16* src, int stride, int tid){
    #pragma unroll
    for (int j = 0; j < 4; j++){
        int i = tid + j * 128;
        int r = i >> 2, seg = (i & 3) * 8;
        cp16(dst + (r * LDAe + seg) * 2, src + (long)r * stride + seg);
    }
}

// =====================================================================
// P1: x -> bf16 hi/lo
// =====================================================================
__global__ __launch_bounds__(256) void prep_x(const float* __restrict__ x)
{
    int i = blockIdx.x * 256 + threadIdx.x;
    float4 v = ((const float4*)x)[i];
    __nv_bfloat16 h0,l0,h1,l1,h2,l2,h3,l3;
    split_bf(v.x,h0,l0); split_bf(v.y,h1,l1); split_bf(v.z,h2,l2); split_bf(v.w,h3,l3);
    ((__nv_bfloat162*)g_xhi)[i*2+0] = __halves2bfloat162(h0,h1);
    ((__nv_bfloat162*)g_xhi)[i*2+1] = __halves2bfloat162(h2,h3);
    ((__nv_bfloat162*)g_xlo)[i*2+0] = __halves2bfloat162(l0,l1);
    ((__nv_bfloat162*)g_xlo)[i*2+1] = __halves2bfloat162(l2,l3);
}

// =====================================================================
// P2: transpose+convert weights
// =====================================================================
__global__ __launch_bounds__(256) void prep_w(
    const float* __restrict__ wq, const float* __restrict__ wk,
    const float* __restrict__ wv, const float* __restrict__ wo)
{
    __shared__ float s[64][65];
    int bx = blockIdx.x;
    int k0 = blockIdx.y * 64;
    const float* W; __nv_bfloat16 *Dh, *Dl; int n0; int dstRow0;
    if (bx < 24) {
        int ng0 = bx * 64; int mat = ng0 >> 9;
        W = (mat == 0) ? wq : (mat == 1) ? wk : wv;
        n0 = ng0 & 511; dstRow0 = ng0;
        Dh = g_wqkvT_hi; Dl = g_wqkvT_lo;
    } else {
        W = wo; n0 = (bx - 24) * 64; dstRow0 = n0;
        Dh = g_woT_hi; Dl = g_woT_lo;
    }
    int tid = threadIdx.x;
    #pragma unroll
    for (int i = 0; i < 4; i++){
        int r = i * 16 + (tid >> 4);
        int c = (tid & 15) * 4;
        float4 v = *(const float4*)(W + (k0 + r) * 512 + n0 + c);
        s[r][c+0]=v.x; s[r][c+1]=v.y; s[r][c+2]=v.z; s[r][c+3]=v.w;
    }
    __syncthreads();
    #pragma unroll
    for (int i = 0; i < 4; i++){
        int rn = i * 16 + (tid >> 4);
        int ck = (tid & 15) * 4;
        __nv_bfloat16 h[4], l[4];
        #pragma unroll
        for (int j = 0; j < 4; j++) split_bf(s[ck + j][rn], h[j], l[j]);
        int off = (dstRow0 + rn) * 512 + k0 + ck;
        *(__nv_bfloat162*)(Dh + off)     = __halves2bfloat162(h[0], h[1]);
        *(__nv_bfloat162*)(Dh + off + 2) = __halves2bfloat162(h[2], h[3]);
        *(__nv_bfloat162*)(Dl + off)     = __halves2bfloat162(l[0], l[1]);
        *(__nv_bfloat162*)(Dl + off + 2) = __halves2bfloat162(l[2], l[3]);
    }
}

// =====================================================================
// P3: precompute Toeplitz tiles (64 rows x 32 cols, padded LDAe), hi/lo.
// =====================================================================
__global__ __launch_bounds__(256) void prep_toep(const float* __restrict__ sbasis)
{
    const int didx = blockIdx.x;      // 0..31
    const int head = blockIdx.y;      // 0..7
    const int diff = didx * 32 - 32;
    __nv_bfloat16* th = g_toep_hi + (head * 32 + didx) * 2560;
    __nv_bfloat16* tl = g_toep_lo + (head * 32 + didx) * 2560;
    for (int i = threadIdx.x; i < 64 * 32; i += 256){
        int r = i >> 5, cc = i & 31;
        int lag = diff + r - cc;
        float v = (lag >= 0 && lag < 1024) ? sbasis[lag * 8 + head] : 0.0f;
        __nv_bfloat16 hv, lv; split_bf(v, hv, lv);
        th[r * LDAe + cc] = hv;
        tl[r * LDAe + cc] = lv;
    }
}

// =====================================================================
// K1: QKV projection GEMM — 4 warps, warp tile 64x64, cp.async 2-stage.
// =====================================================================
__global__ __launch_bounds__(128) void proj_mma(
    const float* __restrict__ bq, const float* __restrict__ bk, const float* __restrict__ bv)
{
    extern __shared__ char sm[];
    const uint32_t sb = smem_u32(sm);
    const int tid = threadIdx.x;
    const int lane = tid & 31, wid = tid >> 5;
    const int warpM = wid & 1, warpN = wid >> 1;
    const int row0 = blockIdx.y * 128;
    const int n0   = blockIdx.x * 128;

    float acc[4][8][4] = {};

    auto issue = [&](int c){
        uint32_t tb = sb + (c & 1) * BUF_B;
        int k0 = c * 32;
        load_tile_async128(tb,            g_xhi + (long)row0*512 + k0, 512, tid);
        load_tile_async128(tb +   TILE_B, g_xlo + (long)row0*512 + k0, 512, tid);
        load_tile_async128(tb + 2*TILE_B, g_wqkvT_hi + (long)n0*512 + k0, 512, tid);
        load_tile_async128(tb + 3*TILE_B, g_wqkvT_lo + (long)n0*512 + k0, 512, tid);
        CP_COMMIT();
    };

    issue(0);
    for (int c = 0; c < 16; c++){
        if (c + 1 < 16){ issue(c + 1); CP_WAIT1(); } else { CP_WAIT0(); }
        __syncthreads();
        uint32_t o = sb + (c & 1) * BUF_B;
        mma_chunk_4w(o, o + TILE_B, o + 2*TILE_B, o + 3*TILE_B, warpM, warpN, lane, acc);
        __syncthreads();
    }

    const int g   = lane >> 2;
    const int tig = lane & 3;
    const int nwarp = n0 + warpN * 64;
    const int mat  = nwarp >> 9;
    const int head = (nwarp >> 6) & 7;
    const int mrow = row0 + warpM * 64;

    if (mat == 0){
        #pragma unroll
        for (int mt = 0; mt < 4; mt++)
            #pragma unroll
            for (int nt = 0; nt < 8; nt++){
                int col = nt * 8 + tig * 2;
                float b0 = bq[(nwarp & 511) + col], b1 = bq[(nwarp & 511) + col + 1];
                #pragma unroll
                for (int rr = 0; rr < 2; rr++){
                    int row = mrow + mt*16 + g + rr*8;
                    int b = row >> 10, l = row & 1023;
                    float2 o; o.x = acc[mt][nt][rr*2+0] + b0; o.y = acc[mt][nt][rr*2+1] + b1;
                    *(float2*)(g_q + (((long)(b*8+head) << 10) + l) * 64 + col) = o;
                }
            }
    } else {
        const float sc = (mat == 1) ? 0.125f : 1.0f;
        const float* bias = (mat == 1) ? bk : bv;
        __nv_bfloat16* Dh = (mat == 1) ? g_ktr_hi : g_vtr_hi;
        __nv_bfloat16* Dl = (mat == 1) ? g_ktr_lo : g_vtr_lo;
        #pragma unroll
        for (int mt = 0; mt < 4; mt++)
            #pragma unroll
            for (int nt = 0; nt < 8; nt++){
                int col = nt * 8 + tig * 2;
                float b0 = bias[(nwarp & 511) + col], b1 = bias[(nwarp & 511) + col + 1];
                #pragma unroll
                for (int rr = 0; rr < 2; rr++){
                    int row = mrow + mt*16 + g + rr*8;
                    int b = row >> 10, l = row & 1023;
                    int bh = b * 8 + head;
                    float v0 = (acc[mt][nt][rr*2+0] + b0) * sc;
                    float v1 = (acc[mt][nt][rr*2+1] + b1) * sc;
                    __nv_bfloat16 h0,l0,h1,l1;
                    split_bf(v0,h0,l0); split_bf(v1,h1,l1);
                    long i0 = (((long)bh*64 + col)   << 10) + l;
                    long i1 = (((long)bh*64 + col+1) << 10) + l;
                    Dh[i0] = h0; Dl[i0] = l0;
                    Dh[i1] = h1; Dl[i1] = l1;
                }
            }
    }
}

// =====================================================================
// K2: causal Toeplitz conv GEMM, balanced + cp.async.
// =====================================================================
#define ATILE_B 5120               // 64*40*2
#define BUFC_B  30720              // Ah | Al | Bh | Bl

__global__ __launch_bounds__(256) void conv_mma()
{
    extern __shared__ char sm[];
    const uint32_t sb = smem_u32(sm);
    const int tid = threadIdx.x;
    const int lane = tid & 31, wid = tid >> 5;
    const int warpM = wid & 1, warpN = wid >> 1;
    const int pair = blockIdx.x;     // 0..7
    const int bh   = blockIdx.y;     // 0..15
    const int head = bh & 7;

    const __nv_bfloat16* kh = g_ktr_hi + (long)bh * 64 * 1024;
    const __nv_bfloat16* kl = g_ktr_lo + (long)bh * 64 * 1024;
    const __nv_bfloat16* vh = g_vtr_hi + (long)bh * 64 * 1024;
    const __nv_bfloat16* vl = g_vtr_lo + (long)bh * 64 * 1024;

    #pragma unroll 1
    for (int s = 0; s < 2; s++){
        const int tile = s ? (15 - pair) : pair;
        const int L0 = tile * 64;
        const int NC = 2 * tile + 2;

        float acc[2][4][4] = {};

        auto issue = [&](int c){
            uint32_t tb = sb + (c & 1) * BUFC_B;
            int T0 = c * 32;
            int didx = 2 * tile - c + 1;
            const __nv_bfloat16* th = g_toep_hi + (head * 32 + didx) * 2560;
            const __nv_bfloat16* tl = g_toep_lo + (head * 32 + didx) * 2560;
            {
                int r = tid >> 2, seg = (tid & 3) * 8;
                int off = r * LDAe + seg;
                cp16(tb + off * 2, th + off);
                cp16(tb + ATILE_B + off * 2, tl + off);
            }
            #pragma unroll
            for (int j = 0; j < 2; j++){
                int i = tid + j * 256;
                int r = i >> 2, seg = (i & 3) * 8;
                const __nv_bfloat16* sh = (r < 64) ? kh + ((long)r << 10) : vh + ((long)(r - 64) << 10);
                const __nv_bfloat16* sl = (r < 64) ? kl + ((long)r << 10) : vl + ((long)(r - 64) << 10);
                cp16(tb + 2*ATILE_B + (r * LDAe + seg) * 2, sh + T0 + seg);
                cp16(tb + 2*ATILE_B + TILE_B + (r * LDAe + seg) * 2, sl + T0 + seg);
            }
            CP_COMMIT();
        };

        issue(0);
        for (int c = 0; c < NC; c++){
            if (c + 1 < NC){ issue(c + 1); CP_WAIT1(); } else { CP_WAIT0(); }
            __syncthreads();
            uint32_t o = sb + (c & 1) * BUFC_B;
            mma_chunk64(o, o + ATILE_B, o + 2*ATILE_B, o + 2*ATILE_B + TILE_B,
                        warpM, warpN, lane, acc);
            __syncthreads();
        }

        const int g = lane >> 2, tig = lane & 3;
        #pragma unroll
        for (int mt = 0; mt < 2; mt++)
            #pragma unroll
            for (int nt = 0; nt < 4; nt++){
                int n = warpN * 32 + nt * 8 + tig * 2;
                float* Dst = (n < 64) ? g_kc : g_vc;
                int col = n & 63;
                #pragma unroll
                for (int rr = 0; rr < 2; rr++){
                    int l = L0 + warpM*32 + mt*16 + g + rr*8;
                    float2 o; o.x = acc[mt][nt][rr*2+0]; o.y = acc[mt][nt][rr*2+1];
                    *(float2*)(Dst + (((long)bh << 10) + l) * 64 + col) = o;
                }
            }
        __syncthreads();
    }
}

// =====================================================================
// K3: gates
// =====================================================================
__global__ __launch_bounds__(256) void gate_kernel(
    const float* __restrict__ wg, const float* __restrict__ wgb)
{
    __shared__ float Wg[64][64];
    const int tid = threadIdx.x;
    for (int i = tid; i < 4096; i += 256) Wg[i >> 6][i & 63] = wg[i];
    __syncthreads();

    const int gidx = blockIdx.x * 256 + tid;
    const float4* k4 = (const float4*)(g_kc + (long)gidx * 64);
    const float4* v4 = (const float4*)(g_vc + (long)gidx * 64);
    float kreg[64], vreg[64];
    #pragma unroll
    for (int n = 0; n < 16; n++){
        float4 a = k4[n];
        kreg[n*4+0]=a.x; kreg[n*4+1]=a.y; kreg[n*4+2]=a.z; kreg[n*4+3]=a.w;
        float4 b = v4[n];
        vreg[n*4+0]=b.x; vreg[n*4+1]=b.y; vreg[n*4+2]=b.z; vreg[n*4+3]=b.w;
    }
    float acc = 0.0f;
    for (int m = 0; m < 64; m++){
        float dot = 0.0f;
        #pragma unroll
        for (int n = 0; n < 64; n++) dot += Wg[m][n] * kreg[n];
        acc += vreg[m] * dot;
    }
    acc += wgb[0];
    float rl = fmaxf(acc, 0.0f);
    g_gate[gidx] = rl * rl + EPSF;
}

// =====================================================================
// K4: scans
// =====================================================================
__device__ __forceinline__ void block_scan_1024(float* arr, float* wsum)
{
    const int tid = threadIdx.x;
    const int lane = tid & 31, wid = tid >> 5;
    float v0 = arr[tid*4+0], v1 = arr[tid*4+1], v2 = arr[tid*4+2], v3 = arr[tid*4+3];
    v1 += v0; v2 += v1; v3 += v2;
    float s = v3;
    #pragma unroll
    for (int o = 1; o < 32; o <<= 1) {
        float t = __shfl_up_sync(0xffffffff, s, o);
        if (lane >= o) s += t;
    }
    float excl = s - v3;
    if (lane == 31) wsum[wid] = s;
    __syncthreads();
    if (wid == 0) {
        float ws = (lane < 8) ? wsum[lane] : 0.0f;
        #pragma unroll
        for (int o = 1; o < 8; o <<= 1) {
            float t = __shfl_up_sync(0xffffffff, ws, o);
            if (lane >= o) ws += t;
        }
        if (lane < 8) wsum[lane] = ws;
    }
    __syncthreads();
    float base = ((wid > 0) ? wsum[wid - 1] : 0.0f) + excl;
    arr[tid*4+0] = v0 + base; arr[tid*4+1] = v1 + base;
    arr[tid*4+2] = v2 + base; arr[tid*4+3] = v3 + base;
    __syncthreads();
}

__global__ __launch_bounds__(256) void scan_kernel()
{
    __shared__ float g[1024];
    __shared__ float p[1024];
    __shared__ float r[1024];
    __shared__ float ws[8];
    const int bh = blockIdx.x;
    const int tid = threadIdx.x;
    const float* gin = g_gate + bh * 1024;
    for (int i = tid; i < 1024; i += 256) { float v = gin[i]; g[i] = v; p[i] = v; }
    __syncthreads();
    block_scan_1024(p, ws);
    for (int i = tid; i < 1024; i += 256) r[i] = 1.0f / (p[i] + EPSF);
    __syncthreads();
    for (int i = tid; i < 1024; i += 256) p[i] = r[i];
    __syncthreads();
    block_scan_1024(p, ws);
    float total = p[1023];
    for (int i = tid; i < 1024; i += 256) {
        float c = total - p[i] + r[i];
        g_w[bh * 1024 + i] = g[i] * c;
    }
}

// =====================================================================
// K5: S partials (8 t-chunks of 128)
// =====================================================================
__global__ __launch_bounds__(256) void Spart_kernel()
{
    __shared__ float Vs[64][68];
    __shared__ float Ks[64][68];
    const int tc = blockIdx.x, bh = blockIdx.y;
    const float* vin = g_vc + (long)bh * Ll * hh;
    const float* kin = g_kc + (long)bh * Ll * hh;
    const float* wt  = g_w  + bh * Ll;
    const int tid = threadIdx.x;
    const int tx = tid & 15, ty = tid >> 4;
    float acc[4][4] = {};

    for (int T0 = tc * 128; T0 < tc * 128 + 128; T0 += 64) {
        for (int i = tid; i < 64 * 16; i += 256) {
            int rrow = i >> 4, c = (i & 15) << 2;
            float w = wt[T0 + rrow];
            float4 vv = *(const float4*)(vin + (T0 + rrow) * 64 + c);
            vv.x *= w; vv.y *= w; vv.z *= w; vv.w *= w;
            *(float4*)&Vs[rrow][c] = vv;
            *(float4*)&Ks[rrow][c] = *(const float4*)(kin + (T0 + rrow) * 64 + c);
        }
        __syncthreads();
        #pragma unroll 4
        for (int tt = 0; tt < 64; tt++) {
            float4 a4 = *(const float4*)&Vs[tt][ty * 4];
            float4 b4 = *(const float4*)&Ks[tt][tx * 4];
            float aa[4] = {a4.x, a4.y, a4.z, a4.w};
            float bb[4] = {b4.x, b4.y, b4.z, b4.w};
            #pragma unroll
            for (int i = 0; i < 4; i++)
                #pragma unroll
                for (int j = 0; j < 4; j++)
                    acc[i][j] += aa[i] * bb[j];
        }
        __syncthreads();
    }
    float* dst = g_Spart + (tc * 16 + bh) * 4096;
    #pragma unroll
    for (int i = 0; i < 4; i++)
        #pragma unroll
        for (int j = 0; j < 4; j++)
            dst[(ty * 4 + i) * 64 + tx * 4 + j] = acc[i][j];
}

// =====================================================================
// K6: ctxt = q @ S, normalize, bf16 hi/lo unit
// =====================================================================
__global__ __launch_bounds__(256) void ctxt_kernel()
{
    __shared__ float Ss[64][65];
    const int b = blockIdx.z, head = blockIdx.y, lc = blockIdx.x;
    const int bh = b * Hh + head;
    const int tid = threadIdx.x;
    for (int i = tid; i < 4096; i += 256) {
        float s = 0.0f;
        #pragma unroll
        for (int p = 0; p < 8; p++) s += g_Spart[(p * 16 + bh) * 4096 + i];
        Ss[i >> 6][i & 63] = s;
    }
    __syncthreads();
    const int l = lc * 256 + tid;
    const float* qrow = g_q + ((long)bh * Ll + l) * hh;
    float out[64];
    #pragma unroll
    for (int e = 0; e < 64; e++) out[e] = 0.0f;
    for (int d = 0; d < 64; d++) {
        float qd = qrow[d];
        #pragma unroll
        for (int e = 0; e < 64; e++) out[e] += qd * Ss[d][e];
    }
    float nrm = 0.0f;
    #pragma unroll
    for (int e = 0; e < 64; e++) nrm += out[e] * out[e];
    float inv = 1.0f / fmaxf(sqrtf(nrm), EPSF);
    long off = ((long)(b * 1024 + l)) * 512 + head * 64;
    #pragma unroll
    for (int e = 0; e < 64; e += 2){
        float a = out[e] * inv, c = out[e+1] * inv;
        __nv_bfloat16 ah, al, ch, cl;
        split_bf(a, ah, al); split_bf(c, ch, cl);
        *(__nv_bfloat162*)(g_uhi + off + e) = __halves2bfloat162(ah, ch);
        *(__nv_bfloat162*)(g_ulo + off + e) = __halves2bfloat162(al, cl);
    }
}

// =====================================================================
// K7: output projection GEMM + cp.async (8-warp)
// =====================================================================
__global__ __launch_bounds__(256) void out_mma(
    const float* __restrict__ bo, float* __restrict__ out)
{
    extern __shared__ char sm[];
    const uint32_t sb = smem_u32(sm);
    const int tid = threadIdx.x;
    const int lane = tid & 31, wid = tid >> 5;
    const int warpM = wid & 3, warpN = wid >> 2;
    const int row0 = blockIdx.y * 128;
    const int n0   = blockIdx.x * 128;

    float acc[2][8][4] = {};

    auto issue = [&](int c){
        uint32_t tb = sb + (c & 1) * BUF_B;
        int k0 = c * 32;
        load_tile_async(tb,            g_uhi + (long)row0*512 + k0, 512, tid);
        load_tile_async(tb +   TILE_B, g_ulo + (long)row0*512 + k0, 512, tid);
        load_tile_async(tb + 2*TILE_B, g_woT_hi + (long)n0*512 + k0, 512, tid);
        load_tile_async(tb + 3*TILE_B, g_woT_lo + (long)n0*512 + k0, 512, tid);
        CP_COMMIT();
    };

    issue(0);
    for (int c = 0; c < 16; c++){
        if (c + 1 < 16){ issue(c + 1); CP_WAIT1(); } else { CP_WAIT0(); }
        __syncthreads();
        uint32_t o = sb + (c & 1) * BUF_B;
        mma_chunk(o, o + TILE_B, o + 2*TILE_B, o + 3*TILE_B, warpM, warpN, lane, acc);
        __syncthreads();
    }

    const int g = lane >> 2, tig = lane & 3;
    #pragma unroll
    for (int mt = 0; mt < 2; mt++)
        #pragma unroll
        for (int nt = 0; nt < 8; nt++){
            int col = n0 + warpN*64 + nt*8 + tig*2;
            float b0 = bo[col], b1 = bo[col+1];
            #pragma unroll
            for (int rr = 0; rr < 2; rr++){
                int row = row0 + warpM*32 + mt*16 + g + rr*8;
                float2 o; o.x = acc[mt][nt][rr*2+0] + b0; o.y = acc[mt][nt][rr*2+1] + b1;
                *(float2*)(out + (long)row * 512 + col) = o;
            }
        }
}

// =====================================================================
extern "C" void kernel_launch(void* const* d_in, const int* in_sizes, int n_in,
                              void* d_out, int out_size)
{
    const float* x   = (const float*)d_in[0];
    const float* sb  = (const float*)d_in[1];
    const float* wq  = (const float*)d_in[2];
    const float* bq  = (const float*)d_in[3];
    const float* wk  = (const float*)d_in[4];
    const float* bk  = (const float*)d_in[5];
    const float* wv  = (const float*)d_in[6];
    const float* bv  = (const float*)d_in[7];
    const float* wo  = (const float*)d_in[8];
    const float* bo  = (const float*)d_in[9];
    const float* wg  = (const float*)d_in[10];
    const float* wgb = (const float*)d_in[11];
    float* out = (float*)d_out;

    const int GEMM_SMEM = 2 * BUF_B;          // 81920
    const int CONV_SMEM = 2 * BUFC_B;         // 61440

    cudaFuncSetAttribute(proj_mma, cudaFuncAttributeMaxDynamicSharedMemorySize, GEMM_SMEM);
    cudaFuncSetAttribute(conv_mma, cudaFuncAttributeMaxDynamicSharedMemorySize, CONV_SMEM);
    cudaFuncSetAttribute(out_mma,  cudaFuncAttributeMaxDynamicSharedMemorySize, GEMM_SMEM);

    prep_x<<<1024, 256>>>(x);
    prep_w<<<dim3(32, 8), 256>>>(wq, wk, wv, wo);
    prep_toep<<<dim3(32, 8), 256>>>(sb);
    proj_mma<<<dim3(12, 16), 128, GEMM_SMEM>>>(bq, bk, bv);
    conv_mma<<<dim3(8, 16), 256, CONV_SMEM>>>();
    gate_kernel<<<64, 256>>>(wg, wgb);
    scan_kernel<<<16, 256>>>();
    Spart_kernel<<<dim3(8, 16), 256>>>();
    ctxt_kernel<<<dim3(4, 8, 2), 256>>>();
    out_mma<<<dim3(4, 16), 256, GEMM_SMEM>>>(bo, out);
}